// round 11
// baseline (speedup 1.0000x reference)
#include <cuda_runtime.h>
#include <cuda_fp16.h>
#include <math.h>
#include <stdint.h>

#define BSZ   512
#define LEN   100
#define NCAND 64
#define DIM   256
#define KIN   32

typedef unsigned long long u64;

// Scratch (no allocations allowed)
__device__ float  g_inter[BSZ * KIN * DIM];
__device__ float  g_scores[BSZ * KIN * LEN];        // [b][k][l]
__device__ __half g_i1[BSZ * KIN * DIM];            // interest splits
__device__ __half g_i2[BSZ * KIN * DIM];
__device__ __half g_h1[256 * 256];                  // W splits
__device__ __half g_h2[256 * 256];
__device__ __half g_p1[BSZ * LEN * DIM];            // tanh(proj) splits (26MB each)
__device__ __half g_p2[BSZ * LEN * DIM];
__device__ __half g_x1[BSZ * LEN * DIM];            // hist splits
__device__ __half g_x2[BSZ * LEN * DIM];

// ---- packed fp32x2 helpers --------------------------------------------------
__device__ __forceinline__ u64 ffma2(u64 a, u64 b, u64 c) {
    u64 d;
    asm("fma.rn.f32x2 %0, %1, %2, %3;" : "=l"(d) : "l"(a), "l"(b), "l"(c));
    return d;
}
__device__ __forceinline__ u64 packu(uint32_t a, uint32_t b) {
    u64 r;
    asm("mov.b64 %0, {%1, %2};" : "=l"(r) : "r"(a), "r"(b));
    return r;
}
__device__ __forceinline__ float2 unpack2(u64 v) {
    float2 r;
    asm("mov.b64 {%0, %1}, %2;" : "=f"(r.x), "=f"(r.y) : "l"(v));
    return r;
}

// ---- mma.sync helpers ---------------------------------------------------------
__device__ __forceinline__ uint32_t smem_u32(const void* p) {
    uint32_t a;
    asm("{ .reg .u64 t; cvta.to.shared.u64 t, %1; cvt.u32.u64 %0, t; }" : "=r"(a) : "l"(p));
    return a;
}
__device__ __forceinline__ void ldsm4(uint32_t* r, uint32_t addr) {
    asm volatile("ldmatrix.sync.aligned.m8n8.x4.shared.b16 {%0,%1,%2,%3}, [%4];"
                 : "=r"(r[0]), "=r"(r[1]), "=r"(r[2]), "=r"(r[3]) : "r"(addr) : "memory");
}
__device__ __forceinline__ void ldsm4t(uint32_t* r, uint32_t addr) {
    asm volatile("ldmatrix.sync.aligned.m8n8.x4.trans.shared.b16 {%0,%1,%2,%3}, [%4];"
                 : "=r"(r[0]), "=r"(r[1]), "=r"(r[2]), "=r"(r[3]) : "r"(addr) : "memory");
}
__device__ __forceinline__ void mma16816(float* d, const uint32_t* a, uint32_t b0, uint32_t b1) {
    asm volatile("mma.sync.aligned.m16n8k16.row.col.f32.f16.f16.f32 "
                 "{%0,%1,%2,%3}, {%4,%5,%6,%7}, {%8,%9}, {%0,%1,%2,%3};"
                 : "+f"(d[0]), "+f"(d[1]), "+f"(d[2]), "+f"(d[3])
                 : "r"(a[0]), "r"(a[1]), "r"(a[2]), "r"(a[3]), "r"(b0), "r"(b1));
}

#define SWZ(o) ((o) ^ (((o) >> 3) & 0x70))

__device__ __forceinline__ uint32_t h2_u32(__half a, __half b) {
    __half2 t(a, b);
    return *reinterpret_cast<uint32_t*>(&t);
}
__device__ __forceinline__ void split_pack(float x, float y, uint32_t& lo, uint32_t& hi) {
    const __half ax = __float2half_rn(x), ay = __float2half_rn(y);
    const __half bx = __float2half_rn(x - __half2float(ax));
    const __half by = __float2half_rn(y - __half2float(ay));
    lo = h2_u32(ax, ay);
    hi = h2_u32(bx, by);
}

// ---------------------------------------------------------------------------
// W split: W (fp32) -> 2 fp16 levels
// ---------------------------------------------------------------------------
__global__ void kw_split(const float* __restrict__ W) {
    const int i = blockIdx.x * 256 + threadIdx.x;
    const float a = W[i];
    const __half h1 = __float2half_rn(a);
    g_h1[i] = h1;
    g_h2[i] = __float2half_rn(a - __half2float(h1));
}

// ---------------------------------------------------------------------------
// K1: proj = tanh(hist @ W^T) via mma.sync fp16, 2-level split (3 passes).
// Persists hist splits (g_x1/g_x2, n0==0 CTAs only) and tanh(proj) splits
// (g_p1/g_p2) for downstream reuse. 2 CTAs/SM.
// ---------------------------------------------------------------------------
#define A_OFF  0
#define B_OFF  32768
#define LVL    16384
#define K1_SMEM (65536 + 1024)

__global__ void __launch_bounds__(256, 2) k1_mma(const float* __restrict__ hist) {
    extern __shared__ char smem_raw[];
    const int tid = threadIdx.x;
    const int wid = tid >> 5;
    const int lane = tid & 31;
    const int warp_m = wid >> 2;
    const int warp_n = wid & 3;
    const int m0 = blockIdx.y * 128;
    const int n0 = blockIdx.x * 128;
    const bool store_x = (blockIdx.x == 0);

    const uint32_t sb_raw = smem_u32(smem_raw);
    const uint32_t sb = (sb_raw + 1023u) & ~1023u;
    char* smem = smem_raw + (sb - sb_raw);

    const int g  = lane >> 3;
    const int rw = lane & 7;

    float acc[4][4][4];
#pragma unroll
    for (int mt = 0; mt < 4; mt++)
#pragma unroll
        for (int nt = 0; nt < 4; nt++)
#pragma unroll
            for (int i = 0; i < 4; i++) acc[mt][nt][i] = 0.f;

    for (int kc = 0; kc < 4; kc++) {
#pragma unroll
        for (int t = 0; t < 8; t++) {
            const int idx = tid + t * 256;
            const int r = idx >> 4, c4 = idx & 15;
            const size_t grow = (size_t)(m0 + r) * 256 + kc * 64 + c4 * 4;
            const float4 a = __ldg((const float4*)&hist[grow]);
            uint32_t lx, hx, ly, hy;
            split_pack(a.x, a.y, lx, hx);
            split_pack(a.z, a.w, ly, hy);
            const uint32_t off = SWZ((uint32_t)(r * 128 + c4 * 8));
            *(uint2*)(smem + A_OFF + off)       = make_uint2(lx, ly);
            *(uint2*)(smem + A_OFF + LVL + off) = make_uint2(hx, hy);
            if (store_x) {
                *(uint2*)&g_x1[grow] = make_uint2(lx, ly);
                *(uint2*)&g_x2[grow] = make_uint2(hx, hy);
            }
        }
        {
            const __half* gw[2] = {g_h1, g_h2};
#pragma unroll
            for (int lv = 0; lv < 2; lv++) {
#pragma unroll
                for (int t = 0; t < 4; t++) {
                    const int idx = tid + t * 256;
                    const int n = idx >> 3, u = idx & 7;
                    const uint4 v = *(const uint4*)&gw[lv][(size_t)(n0 + n) * 256 + kc * 64 + u * 8];
                    *(uint4*)(smem + B_OFF + lv * LVL + SWZ((uint32_t)(n * 128 + u * 16))) = v;
                }
            }
        }
        __syncthreads();

#pragma unroll
        for (int ks = 0; ks < 4; ks++) {
            const int k0 = ks * 16;
            uint32_t aoff[4], boff[2];
#pragma unroll
            for (int mt = 0; mt < 4; mt++) {
                const int row = warp_m * 64 + mt * 16 + ((g & 1) << 3) + rw;
                const int kk  = k0 + ((g >> 1) << 3);
                aoff[mt] = sb + A_OFF + SWZ((uint32_t)(row * 128 + kk * 2));
            }
#pragma unroll
            for (int nt2 = 0; nt2 < 2; nt2++) {
                const int row = warp_n * 32 + nt2 * 16 + ((g >> 1) << 3) + rw;
                const int kk  = k0 + ((g & 1) << 3);
                boff[nt2] = sb + B_OFF + SWZ((uint32_t)(row * 128 + kk * 2));
            }

            uint32_t a0[4][4], a1[4][4], b0[2][4], b1[2][4];
#pragma unroll
            for (int mt = 0; mt < 4; mt++) { ldsm4(a0[mt], aoff[mt]); ldsm4(a1[mt], aoff[mt] + LVL); }
#pragma unroll
            for (int nt2 = 0; nt2 < 2; nt2++) { ldsm4(b0[nt2], boff[nt2]); ldsm4(b1[nt2], boff[nt2] + LVL); }

#pragma unroll
            for (int mt = 0; mt < 4; mt++)
#pragma unroll
                for (int nt = 0; nt < 4; nt++) {
                    const int h = nt >> 1, q = (nt & 1) * 2;
                    mma16816(acc[mt][nt], a0[mt], b0[h][q], b0[h][q + 1]);
                    mma16816(acc[mt][nt], a0[mt], b1[h][q], b1[h][q + 1]);
                    mma16816(acc[mt][nt], a1[mt], b0[h][q], b0[h][q + 1]);
                }
        }
        __syncthreads();
    }

    // epilogue: tanh + split + store proj splits
    const int gid = lane >> 2, tig = lane & 3;
#pragma unroll
    for (int mt = 0; mt < 4; mt++) {
#pragma unroll
        for (int nt = 0; nt < 4; nt++) {
            const size_t row = (size_t)(m0 + warp_m * 64 + mt * 16 + gid);
            const int col = n0 + warp_n * 32 + nt * 8 + tig * 2;
            const float t0 = tanhf(acc[mt][nt][0]), t1 = tanhf(acc[mt][nt][1]);
            const float t2 = tanhf(acc[mt][nt][2]), t3 = tanhf(acc[mt][nt][3]);
            uint32_t lo0, hi0, lo1, hi1;
            split_pack(t0, t1, lo0, hi0);
            split_pack(t2, t3, lo1, hi1);
            *(uint32_t*)&g_p1[row * 256 + col]       = lo0;
            *(uint32_t*)&g_p2[row * 256 + col]       = hi0;
            *(uint32_t*)&g_p1[(row + 8) * 256 + col] = lo1;
            *(uint32_t*)&g_p2[(row + 8) * 256 + col] = hi1;
        }
    }
}

// ---------------------------------------------------------------------------
// K2a: scores = proj @ codes^T using PRE-SPLIT proj (pure copies, no cvt).
// ---------------------------------------------------------------------------
__global__ void __launch_bounds__(128) k2a_kernel(const float* __restrict__ codes) {
    __shared__ __align__(16) char Asm[2][16384];
    __shared__ __align__(16) char Bsm[2][4096];

    const int tid = threadIdx.x;
    const int w = tid >> 5;
    const int lane = tid & 31;
    const int m0 = blockIdx.x * 128;
    const int g = lane >> 3, rw = lane & 7;
    const uint32_t sbA = smem_u32(Asm);
    const uint32_t sbB = smem_u32(Bsm);

    float acc[2][4][4];
#pragma unroll
    for (int mt = 0; mt < 2; mt++)
#pragma unroll
        for (int nt = 0; nt < 4; nt++)
#pragma unroll
            for (int i = 0; i < 4; i++) acc[mt][nt][i] = 0.f;

    for (int kc = 0; kc < 4; kc++) {
        // A: direct uint4 copies of pre-split proj
#pragma unroll
        for (int t = 0; t < 8; t++) {
            const int idx = tid + t * 128;           // 0..1023
            const int r = idx >> 3, u = idx & 7;
            const size_t src = (size_t)(m0 + r) * 256 + kc * 64 + u * 8;
            const uint32_t off = SWZ((uint32_t)(r * 128 + u * 16));
            *(uint4*)(Asm[0] + off) = *(const uint4*)&g_p1[src];
            *(uint4*)(Asm[1] + off) = *(const uint4*)&g_p2[src];
        }
        // B: codes fp32 -> split (tiny, 32 rows)
#pragma unroll
        for (int t = 0; t < 4; t++) {
            const int idx = tid + t * 128;
            const int r = idx >> 4, c4 = idx & 15;
            const float4 a = __ldg((const float4*)&codes[(size_t)r * 256 + kc * 64 + c4 * 4]);
            uint32_t lx, hx, ly, hy;
            split_pack(a.x, a.y, lx, hx);
            split_pack(a.z, a.w, ly, hy);
            const uint32_t off = SWZ((uint32_t)(r * 128 + c4 * 8));
            *(uint2*)(Bsm[0] + off) = make_uint2(lx, ly);
            *(uint2*)(Bsm[1] + off) = make_uint2(hx, hy);
        }
        __syncthreads();

#pragma unroll
        for (int ks = 0; ks < 4; ks++) {
            const int k0 = ks * 16;
            uint32_t aoff[2], boff[2];
#pragma unroll
            for (int mt = 0; mt < 2; mt++) {
                const int row = w * 32 + mt * 16 + ((g & 1) << 3) + rw;
                aoff[mt] = sbA + SWZ((uint32_t)(row * 128 + (k0 + ((g >> 1) << 3)) * 2));
            }
#pragma unroll
            for (int nt2 = 0; nt2 < 2; nt2++) {
                const int row = nt2 * 16 + ((g >> 1) << 3) + rw;
                boff[nt2] = sbB + SWZ((uint32_t)(row * 128 + (k0 + ((g & 1) << 3)) * 2));
            }
            uint32_t a0[2][4], a1[2][4], b0[2][4], b1[2][4];
#pragma unroll
            for (int mt = 0; mt < 2; mt++) { ldsm4(a0[mt], aoff[mt]); ldsm4(a1[mt], aoff[mt] + 16384); }
#pragma unroll
            for (int nt2 = 0; nt2 < 2; nt2++) { ldsm4(b0[nt2], boff[nt2]); ldsm4(b1[nt2], boff[nt2] + 4096); }
#pragma unroll
            for (int mt = 0; mt < 2; mt++)
#pragma unroll
                for (int nt = 0; nt < 4; nt++) {
                    const int h = nt >> 1, q = (nt & 1) * 2;
                    mma16816(acc[mt][nt], a0[mt], b0[h][q], b0[h][q + 1]);
                    mma16816(acc[mt][nt], a0[mt], b1[h][q], b1[h][q + 1]);
                    mma16816(acc[mt][nt], a1[mt], b0[h][q], b0[h][q + 1]);
                    mma16816(acc[mt][nt], a1[mt], b1[h][q], b1[h][q + 1]);
                }
        }
        __syncthreads();
    }

    const int gid = lane >> 2, tig = lane & 3;
#pragma unroll
    for (int mt = 0; mt < 2; mt++) {
#pragma unroll
        for (int nt = 0; nt < 4; nt++) {
            const int col = nt * 8 + tig * 2;
#pragma unroll
            for (int half = 0; half < 2; half++) {
                const int M = m0 + w * 32 + mt * 16 + gid + half * 8;
                const int b = M / 100, l = M - b * 100;
                float* dst = g_scores + (size_t)b * 3200 + l;
                dst[(size_t)col * 100]       = acc[mt][nt][half * 2];
                dst[(size_t)(col + 1) * 100] = acc[mt][nt][half * 2 + 1];
            }
        }
    }
}

// ---------------------------------------------------------------------------
// K2F: per-batch fused softmax(scores) -> interests, using PRE-SPLIT hist.
// ---------------------------------------------------------------------------
__global__ void __launch_bounds__(128) k2f(const int* __restrict__ numInt) {
    __shared__ __align__(16) char Asm[16384];
    __shared__ __align__(16) char Bsm[32768];

    const int b = blockIdx.x;
    const int tid = threadIdx.x;
    const int w = tid >> 5;
    const int lane = tid & 31;
    const int g = lane >> 3, rw = lane & 7;
    const uint32_t sbA = smem_u32(Asm);
    const uint32_t sbB = smem_u32(Bsm);

    float* sc = (float*)Bsm;
    {
        const float* src = g_scores + (size_t)b * 3200;
        for (int idx = tid; idx < 3200; idx += 128) sc[idx] = src[idx];
    }
    __syncthreads();
    {
        const int ni = numInt[b];
        for (int k = w; k < 32; k += 4) {
            if (k >= ni) {
                for (int l = lane; l < LEN; l += 32) sc[k * 100 + l] = 0.01f;
            } else {
                float m = -3.4e38f;
                for (int l = lane; l < LEN; l += 32) m = fmaxf(m, sc[k * 100 + l]);
#pragma unroll
                for (int off = 16; off; off >>= 1)
                    m = fmaxf(m, __shfl_xor_sync(0xffffffffu, m, off));
                float s = 0.f;
                for (int l = lane; l < LEN; l += 32) {
                    float e = expf(sc[k * 100 + l] - m);
                    sc[k * 100 + l] = e;
                    s += e;
                }
#pragma unroll
                for (int off = 16; off; off >>= 1) s += __shfl_xor_sync(0xffffffffu, s, off);
                for (int l = lane; l < LEN; l += 32) sc[k * 100 + l] = sc[k * 100 + l] / s;
            }
        }
    }
    __syncthreads();

    for (int idx = tid; idx < 2048; idx += 128) {
        const int k = idx >> 6;
        const int l2 = (idx & 63) * 2;
        const float v0 = (l2 < 100) ? sc[k * 100 + l2] : 0.f;
        const float v1 = (l2 + 1 < 100) ? sc[k * 100 + l2 + 1] : 0.f;
        uint32_t lo, hi;
        split_pack(v0, v1, lo, hi);
        const int h = l2 >> 6, ll = l2 & 63;
        const uint32_t off = SWZ((uint32_t)((h * 32 + k) * 128 + ll * 2));
        *(uint32_t*)(Asm + off)        = lo;
        *(uint32_t*)(Asm + 8192 + off) = hi;
    }
    __syncthreads();

    float acc[2][8][4];
#pragma unroll
    for (int mt = 0; mt < 2; mt++)
#pragma unroll
        for (int nt = 0; nt < 8; nt++)
#pragma unroll
            for (int i = 0; i < 4; i++) acc[mt][nt][i] = 0.f;

    for (int ch = 0; ch < 4; ch++) {
        const int l0 = ch * 32;
        // hist chunk: direct uint4 copies of pre-split hist (zero-pad l>=100)
#pragma unroll
        for (int t = 0; t < 8; t++) {
            const int idx = tid + t * 128;            // 0..1023
            const int lr = idx >> 5, c8 = idx & 31;   // d = c8*8
            const int l = l0 + lr;
            const int d = c8 * 8;
            uint4 v1 = make_uint4(0, 0, 0, 0), v2 = make_uint4(0, 0, 0, 0);
            if (l < LEN) {
                const size_t src = (size_t)(b * 100 + l) * 256 + d;
                v1 = *(const uint4*)&g_x1[src];
                v2 = *(const uint4*)&g_x2[src];
            }
            const int p = d >> 6, dcol = d & 63;
            const uint32_t off = p * 4096 + SWZ((uint32_t)(lr * 128 + dcol * 2));
            *(uint4*)(Bsm + off)         = v1;
            *(uint4*)(Bsm + 16384 + off) = v2;
        }
        __syncthreads();

#pragma unroll
        for (int ks2 = 0; ks2 < 2; ks2++) {
            const int kk = l0 + ks2 * 16;
            const int half = kk >> 6, lloc = kk & 63;

            uint32_t a0[2][4], a1[2][4];
#pragma unroll
            for (int mt = 0; mt < 2; mt++) {
                const int row = mt * 16 + ((g & 1) << 3) + rw;
                const uint32_t ao = SWZ((uint32_t)((half * 32 + row) * 128 + (lloc + ((g >> 1) << 3)) * 2));
                ldsm4(a0[mt], sbA + ao);
                ldsm4(a1[mt], sbA + 8192 + ao);
            }

            const int trow = ks2 * 16 + (lane & 7) + ((lane >> 3) & 1) * 8;
            const int tcolb = ((lane >> 4) & 1) * 8;
#pragma unroll
            for (int ntt = 0; ntt < 4; ntt++) {
                const uint32_t bo = w * 4096 + SWZ((uint32_t)(trow * 128 + (ntt * 16 + tcolb) * 2));
                uint32_t bl0[4], bl1[4];
                ldsm4t(bl0, sbB + bo);
                ldsm4t(bl1, sbB + 16384 + bo);
#pragma unroll
                for (int mt = 0; mt < 2; mt++) {
                    float* c0 = acc[mt][ntt * 2];
                    float* c1 = acc[mt][ntt * 2 + 1];
                    mma16816(c0, a0[mt], bl0[0], bl0[1]);
                    mma16816(c0, a0[mt], bl1[0], bl1[1]);
                    mma16816(c0, a1[mt], bl0[0], bl0[1]);
                    mma16816(c0, a1[mt], bl1[0], bl1[1]);
                    mma16816(c1, a0[mt], bl0[2], bl0[3]);
                    mma16816(c1, a0[mt], bl1[2], bl1[3]);
                    mma16816(c1, a1[mt], bl0[2], bl0[3]);
                    mma16816(c1, a1[mt], bl1[2], bl1[3]);
                }
            }
        }
        __syncthreads();
    }

    const int gid = lane >> 2, tig = lane & 3;
    float* Ib = g_inter + (size_t)b * KIN * DIM;
    __half* I1 = g_i1 + (size_t)b * KIN * DIM;
    __half* I2 = g_i2 + (size_t)b * KIN * DIM;
#pragma unroll
    for (int mt = 0; mt < 2; mt++) {
#pragma unroll
        for (int nt = 0; nt < 8; nt++) {
            const int k = mt * 16 + gid;
            const int d = w * 64 + nt * 8 + tig * 2;
#pragma unroll
            for (int hh = 0; hh < 2; hh++) {
                const int kk = k + hh * 8;
                const float vx = acc[mt][nt][hh * 2], vy = acc[mt][nt][hh * 2 + 1];
                *(float2*)&Ib[(size_t)kk * 256 + d] = make_float2(vx, vy);
                uint32_t lo, hi;
                split_pack(vx, vy, lo, hi);
                *(uint32_t*)&I1[(size_t)kk * 256 + d] = lo;
                *(uint32_t*)&I2[(size_t)kk * 256 + d] = hi;
            }
        }
    }
}

// ---------------------------------------------------------------------------
// K4: 2 blocks/batch. w-GEMM + rank exact fp32; user-GEMM via fp16-split mma.
// (unchanged from R8/R10)
// ---------------------------------------------------------------------------
#define K4_SMEM (62464 + 1024)

__global__ __launch_bounds__(256) void k4_kernel(const float* __restrict__ cand,
                                                 const int* __restrict__ catCnt,
                                                 float* __restrict__ out) {
    extern __shared__ char k4raw[];
    const int b = blockIdx.x >> 1;
    const int nbase = (blockIdx.x & 1) * 32;
    const int tid = threadIdx.x;
    const int w = tid >> 5;
    const int lane = tid & 31;

    const uint32_t sbr = smem_u32(k4raw);
    const uint32_t sb = (sbr + 1023u) & ~1023u;
    char* s = k4raw + (sb - sbr);
    float* row_sm  = (float*)(s);
    float* partial = (float*)(s + 8192);
    float* wfull   = (float*)(s + 16384);
    float* wmaskT  = (float*)(s + 17408);
    char*  ism     = s + 21504;
    char*  wmsm    = s + 54272;
    const uint32_t u_ism  = sb + 21504;
    const uint32_t u_wmsm = sb + 54272;

    {
        const uint4* s1 = (const uint4*)(g_i1 + (size_t)b * 8192);
        const uint4* s2 = (const uint4*)(g_i2 + (size_t)b * 8192);
#pragma unroll
        for (int t = 0; t < 4; t++) {
            const int idx = tid + t * 256;
            const int k = idx >> 5, c8 = idx & 31;
            const int d = c8 * 8, p = d >> 6, dloc = d & 63;
            const uint32_t off = p * 4096 + SWZ((uint32_t)(k * 128 + dloc * 2));
            *(uint4*)(ism + off)         = s1[idx];
            *(uint4*)(ism + 16384 + off) = s2[idx];
        }
    }

    u64 ireg2[16];
    {
        const u64* ibase = (const u64*)(g_inter + (size_t)b * 8192 + (size_t)lane * 256 + w * 32);
#pragma unroll
        for (int j = 0; j < 16; j++) ireg2[j] = ibase[j];
    }

    const int cc = catCnt[b];
    int dynK = (int)ceilf(log2f(8.0f * (float)cc));
    dynK = dynK < 1 ? 1 : (dynK > 32 ? 32 : dynK);

    const float* Cb = cand + (size_t)b * NCAND * DIM + (size_t)nbase * DIM;
    for (int n0 = 0; n0 < 32; n0 += 8) {
        const float4* src = (const float4*)(Cb + (size_t)n0 * DIM);
        float4* dst = (float4*)row_sm;
        dst[tid] = src[tid];
        dst[tid + 256] = src[tid + 256];
        __syncthreads();

        u64 p[8];
#pragma unroll
        for (int r = 0; r < 8; r++) p[r] = 0ull;
        const uint4* rbase4 = (const uint4*)row_sm;
#pragma unroll
        for (int j4 = 0; j4 < 8; j4++) {
            const u64 iv0 = ireg2[j4 * 2], iv1 = ireg2[j4 * 2 + 1];
            const int coff = w * 8 + j4;
#pragma unroll
            for (int r = 0; r < 8; r++) {
                const uint4 v = rbase4[r * 64 + coff];
                p[r] = ffma2(iv0, packu(v.x, v.y), p[r]);
                p[r] = ffma2(iv1, packu(v.z, v.w), p[r]);
            }
        }
#pragma unroll
        for (int r = 0; r < 8; r++) {
            float2 t = unpack2(p[r]);
            partial[w * 256 + r * 32 + lane] = t.x + t.y;
        }
        __syncthreads();

        {
            const int k = tid & 31, r = tid >> 5;
            float ssum = 0.f;
#pragma unroll
            for (int ww = 0; ww < 8; ww++) ssum += partial[ww * 256 + r * 32 + k];
            wfull[r * 32 + k] = ssum;
        }
        __syncthreads();

        {
            const float wi = wfull[w * 32 + lane];
            int rank = 0;
#pragma unroll
            for (int j = 0; j < 32; j++) {
                const float wj = __shfl_sync(0xffffffffu, wi, j);
                rank += (wj > wi) || (wj == wi && j < lane);
            }
            wmaskT[(n0 + w) * 32 + lane] = (rank < dynK) ? wi : 0.f;
        }
        __syncthreads();
    }

    {
#pragma unroll
        for (int t = 0; t < 4; t++) {
            const int idx = tid + t * 256;
            const int r = idx >> 5, c = idx & 31;
            const float v = wmaskT[r * 32 + c];
            const __half m1 = __float2half_rn(v);
            const __half m2 = __float2half_rn(v - __half2float(m1));
            const uint32_t off = SWZ((uint32_t)(r * 128 + c * 2));
            *(__half*)(wmsm + off)        = m1;
            *(__half*)(wmsm + 4096 + off) = m2;
        }
    }
    __syncthreads();

    const int g = lane >> 3, rw = lane & 7;
    const int mt = w & 1;
    const int pnl = w >> 1;

    float ua[4][2][4];
#pragma unroll
    for (int ntt = 0; ntt < 4; ntt++)
#pragma unroll
        for (int n8 = 0; n8 < 2; n8++)
#pragma unroll
            for (int i = 0; i < 4; i++) ua[ntt][n8][i] = 0.f;

#pragma unroll
    for (int ks = 0; ks < 2; ks++) {
        const int arow = mt * 16 + ((g & 1) << 3) + rw;
        const int acol = ks * 16 + ((g >> 1) << 3);
        const uint32_t ao = SWZ((uint32_t)(arow * 128 + acol * 2));
        uint32_t am1[4], am2[4];
        ldsm4(am1, u_wmsm + ao);
        ldsm4(am2, u_wmsm + 4096 + ao);

        const int trow = ks * 16 + (lane & 7) + ((lane >> 3) & 1) * 8;
        const int tcolb = ((lane >> 4) & 1) * 8;
#pragma unroll
        for (int ntt = 0; ntt < 4; ntt++) {
            const uint32_t bo = pnl * 4096 + SWZ((uint32_t)(trow * 128 + (ntt * 16 + tcolb) * 2));
            uint32_t bi1[4], bi2[4];
            ldsm4t(bi1, u_ism + bo);
            ldsm4t(bi2, u_ism + 16384 + bo);
#pragma unroll
            for (int n8 = 0; n8 < 2; n8++) {
                float* c = ua[ntt][n8];
                mma16816(c, am1, bi1[n8 * 2], bi1[n8 * 2 + 1]);
                mma16816(c, am1, bi2[n8 * 2], bi2[n8 * 2 + 1]);
                mma16816(c, am2, bi1[n8 * 2], bi1[n8 * 2 + 1]);
            }
        }
    }

    const int gid = lane >> 2, tig = lane & 3;
    float* Ob = out + (size_t)b * NCAND * DIM + (size_t)nbase * DIM;
#pragma unroll
    for (int ntt = 0; ntt < 4; ntt++) {
#pragma unroll
        for (int n8 = 0; n8 < 2; n8++) {
            const int d = pnl * 64 + ntt * 16 + n8 * 8 + tig * 2;
            const int r0 = mt * 16 + gid;
            *(float2*)&Ob[(size_t)r0 * 256 + d]       = make_float2(ua[ntt][n8][0], ua[ntt][n8][1]);
            *(float2*)&Ob[(size_t)(r0 + 8) * 256 + d] = make_float2(ua[ntt][n8][2], ua[ntt][n8][3]);
        }
    }
}

// ---------------------------------------------------------------------------
extern "C" void kernel_launch(void* const* d_in, const int* in_sizes, int n_in,
                              void* d_out, int out_size) {
    (void)in_sizes; (void)n_in; (void)out_size;
    const float* hist  = (const float*)d_in[0];
    const float* cand  = (const float*)d_in[2];
    const int*   numI  = (const int*)d_in[3];
    const int*   catC  = (const int*)d_in[4];
    const float* W     = (const float*)d_in[5];
    const float* codes = (const float*)d_in[6];
    float* out = (float*)d_out;

    static bool attr_set = false;
    if (!attr_set) {
        cudaFuncSetAttribute(k1_mma, cudaFuncAttributeMaxDynamicSharedMemorySize, K1_SMEM);
        cudaFuncSetAttribute(k4_kernel, cudaFuncAttributeMaxDynamicSharedMemorySize, K4_SMEM);
        attr_set = true;
    }

    kw_split<<<256, 256>>>(W);
    k1_mma<<<dim3(2, 400), 256, K1_SMEM>>>(hist);
    k2a_kernel<<<400, 128>>>(codes);
    k2f<<<BSZ, 128>>>(numI);
    k4_kernel<<<2 * BSZ, 256, K4_SMEM>>>(cand, catC, out);
}

// round 12
// speedup vs baseline: 1.1893x; 1.1893x over previous
#include <cuda_runtime.h>
#include <cuda_fp16.h>
#include <math.h>
#include <stdint.h>

#define BSZ   512
#define LEN   100
#define NCAND 64
#define DIM   256
#define KIN   32

typedef unsigned long long u64;

// Scratch (no allocations allowed)
__device__ float  g_proj[BSZ * LEN * DIM];          // 52.4 MB
__device__ float  g_scores[BSZ * KIN * LEN];        // [b][k][l]
__device__ __half g_h1[256 * 256];                  // W splits
__device__ __half g_h2[256 * 256];

// ---- packed fp32x2 helpers --------------------------------------------------
__device__ __forceinline__ u64 ffma2(u64 a, u64 b, u64 c) {
    u64 d;
    asm("fma.rn.f32x2 %0, %1, %2, %3;" : "=l"(d) : "l"(a), "l"(b), "l"(c));
    return d;
}
__device__ __forceinline__ u64 packu(uint32_t a, uint32_t b) {
    u64 r;
    asm("mov.b64 %0, {%1, %2};" : "=l"(r) : "r"(a), "r"(b));
    return r;
}
__device__ __forceinline__ float2 unpack2(u64 v) {
    float2 r;
    asm("mov.b64 {%0, %1}, %2;" : "=f"(r.x), "=f"(r.y) : "l"(v));
    return r;
}

// ---- mma.sync helpers ---------------------------------------------------------
__device__ __forceinline__ uint32_t smem_u32(const void* p) {
    uint32_t a;
    asm("{ .reg .u64 t; cvta.to.shared.u64 t, %1; cvt.u32.u64 %0, t; }" : "=r"(a) : "l"(p));
    return a;
}
__device__ __forceinline__ void ldsm4(uint32_t* r, uint32_t addr) {
    asm volatile("ldmatrix.sync.aligned.m8n8.x4.shared.b16 {%0,%1,%2,%3}, [%4];"
                 : "=r"(r[0]), "=r"(r[1]), "=r"(r[2]), "=r"(r[3]) : "r"(addr) : "memory");
}
__device__ __forceinline__ void ldsm4t(uint32_t* r, uint32_t addr) {
    asm volatile("ldmatrix.sync.aligned.m8n8.x4.trans.shared.b16 {%0,%1,%2,%3}, [%4];"
                 : "=r"(r[0]), "=r"(r[1]), "=r"(r[2]), "=r"(r[3]) : "r"(addr) : "memory");
}
__device__ __forceinline__ void mma16816(float* d, const uint32_t* a, uint32_t b0, uint32_t b1) {
    asm volatile("mma.sync.aligned.m16n8k16.row.col.f32.f16.f16.f32 "
                 "{%0,%1,%2,%3}, {%4,%5,%6,%7}, {%8,%9}, {%0,%1,%2,%3};"
                 : "+f"(d[0]), "+f"(d[1]), "+f"(d[2]), "+f"(d[3])
                 : "r"(a[0]), "r"(a[1]), "r"(a[2]), "r"(a[3]), "r"(b0), "r"(b1));
}

#define SWZ(o) ((o) ^ (((o) >> 3) & 0x70))

__device__ __forceinline__ uint32_t h2_u32(__half a, __half b) {
    __half2 t(a, b);
    return *reinterpret_cast<uint32_t*>(&t);
}
__device__ __forceinline__ void split_pack(float x, float y, uint32_t& lo, uint32_t& hi) {
    const __half ax = __float2half_rn(x), ay = __float2half_rn(y);
    const __half bx = __float2half_rn(x - __half2float(ax));
    const __half by = __float2half_rn(y - __half2float(ay));
    lo = h2_u32(ax, ay);
    hi = h2_u32(bx, by);
}

// ---------------------------------------------------------------------------
// W split
// ---------------------------------------------------------------------------
__global__ void kw_split(const float* __restrict__ W) {
    const int i = blockIdx.x * 256 + threadIdx.x;
    const float a = W[i];
    const __half h1 = __float2half_rn(a);
    g_h1[i] = h1;
    g_h2[i] = __float2half_rn(a - __half2float(h1));
}

// ---------------------------------------------------------------------------
// K1: proj = tanh(hist @ W^T) via mma.sync fp16, 2-level split (3 passes).
// (R10 version, 65us measured)
// ---------------------------------------------------------------------------
#define A_OFF  0
#define B_OFF  32768
#define LVL    16384
#define K1_SMEM (65536 + 1024)

__global__ void __launch_bounds__(256, 2) k1_mma(const float* __restrict__ hist) {
    extern __shared__ char smem_raw[];
    const int tid = threadIdx.x;
    const int wid = tid >> 5;
    const int lane = tid & 31;
    const int warp_m = wid >> 2;
    const int warp_n = wid & 3;
    const int m0 = blockIdx.y * 128;
    const int n0 = blockIdx.x * 128;

    const uint32_t sb_raw = smem_u32(smem_raw);
    const uint32_t sb = (sb_raw + 1023u) & ~1023u;
    char* smem = smem_raw + (sb - sb_raw);

    const int g  = lane >> 3;
    const int rw = lane & 7;

    float acc[4][4][4];
#pragma unroll
    for (int mt = 0; mt < 4; mt++)
#pragma unroll
        for (int nt = 0; nt < 4; nt++)
#pragma unroll
            for (int i = 0; i < 4; i++) acc[mt][nt][i] = 0.f;

    for (int kc = 0; kc < 4; kc++) {
#pragma unroll
        for (int t = 0; t < 8; t++) {
            const int idx = tid + t * 256;
            const int r = idx >> 4, c4 = idx & 15;
            const float4 a = __ldg((const float4*)&hist[(size_t)(m0 + r) * 256 + kc * 64 + c4 * 4]);
            uint32_t lx, hx, ly, hy;
            split_pack(a.x, a.y, lx, hx);
            split_pack(a.z, a.w, ly, hy);
            const uint32_t off = SWZ((uint32_t)(r * 128 + c4 * 8));
            *(uint2*)(smem + A_OFF + off)       = make_uint2(lx, ly);
            *(uint2*)(smem + A_OFF + LVL + off) = make_uint2(hx, hy);
        }
        {
            const __half* gw[2] = {g_h1, g_h2};
#pragma unroll
            for (int lv = 0; lv < 2; lv++) {
#pragma unroll
                for (int t = 0; t < 4; t++) {
                    const int idx = tid + t * 256;
                    const int n = idx >> 3, u = idx & 7;
                    const uint4 v = *(const uint4*)&gw[lv][(size_t)(n0 + n) * 256 + kc * 64 + u * 8];
                    *(uint4*)(smem + B_OFF + lv * LVL + SWZ((uint32_t)(n * 128 + u * 16))) = v;
                }
            }
        }
        __syncthreads();

#pragma unroll
        for (int ks = 0; ks < 4; ks++) {
            const int k0 = ks * 16;
            uint32_t aoff[4], boff[2];
#pragma unroll
            for (int mt = 0; mt < 4; mt++) {
                const int row = warp_m * 64 + mt * 16 + ((g & 1) << 3) + rw;
                const int kk  = k0 + ((g >> 1) << 3);
                aoff[mt] = sb + A_OFF + SWZ((uint32_t)(row * 128 + kk * 2));
            }
#pragma unroll
            for (int nt2 = 0; nt2 < 2; nt2++) {
                const int row = warp_n * 32 + nt2 * 16 + ((g >> 1) << 3) + rw;
                const int kk  = k0 + ((g & 1) << 3);
                boff[nt2] = sb + B_OFF + SWZ((uint32_t)(row * 128 + kk * 2));
            }

            uint32_t a0[4][4], a1[4][4], b0[2][4], b1[2][4];
#pragma unroll
            for (int mt = 0; mt < 4; mt++) { ldsm4(a0[mt], aoff[mt]); ldsm4(a1[mt], aoff[mt] + LVL); }
#pragma unroll
            for (int nt2 = 0; nt2 < 2; nt2++) { ldsm4(b0[nt2], boff[nt2]); ldsm4(b1[nt2], boff[nt2] + LVL); }

#pragma unroll
            for (int mt = 0; mt < 4; mt++)
#pragma unroll
                for (int nt = 0; nt < 4; nt++) {
                    const int h = nt >> 1, q = (nt & 1) * 2;
                    mma16816(acc[mt][nt], a0[mt], b0[h][q], b0[h][q + 1]);
                    mma16816(acc[mt][nt], a0[mt], b1[h][q], b1[h][q + 1]);
                    mma16816(acc[mt][nt], a1[mt], b0[h][q], b0[h][q + 1]);
                }
        }
        __syncthreads();
    }

    const int gid = lane >> 2, tig = lane & 3;
#pragma unroll
    for (int mt = 0; mt < 4; mt++) {
#pragma unroll
        for (int nt = 0; nt < 4; nt++) {
            const int row = m0 + warp_m * 64 + mt * 16 + gid;
            const int col = n0 + warp_n * 32 + nt * 8 + tig * 2;
            float2 v0, v1;
            v0.x = tanhf(acc[mt][nt][0]); v0.y = tanhf(acc[mt][nt][1]);
            v1.x = tanhf(acc[mt][nt][2]); v1.y = tanhf(acc[mt][nt][3]);
            *(float2*)&g_proj[(size_t)row * 256 + col]       = v0;
            *(float2*)&g_proj[(size_t)(row + 8) * 256 + col] = v1;
        }
    }
}

// ---------------------------------------------------------------------------
// K2a: scores = g_proj @ codes^T  (R10 version)
// ---------------------------------------------------------------------------
__global__ void __launch_bounds__(128) k2a_kernel(const float* __restrict__ codes) {
    __shared__ __align__(16) char Asm[2][16384];
    __shared__ __align__(16) char Bsm[2][4096];

    const int tid = threadIdx.x;
    const int w = tid >> 5;
    const int lane = tid & 31;
    const int m0 = blockIdx.x * 128;
    const int g = lane >> 3, rw = lane & 7;
    const uint32_t sbA = smem_u32(Asm);
    const uint32_t sbB = smem_u32(Bsm);

    float acc[2][4][4];
#pragma unroll
    for (int mt = 0; mt < 2; mt++)
#pragma unroll
        for (int nt = 0; nt < 4; nt++)
#pragma unroll
            for (int i = 0; i < 4; i++) acc[mt][nt][i] = 0.f;

    for (int kc = 0; kc < 4; kc++) {
#pragma unroll
        for (int t = 0; t < 16; t++) {
            const int idx = tid + t * 128;
            const int r = idx >> 4, c4 = idx & 15;
            const float4 a = __ldg((const float4*)&g_proj[(size_t)(m0 + r) * 256 + kc * 64 + c4 * 4]);
            uint32_t lx, hx, ly, hy;
            split_pack(a.x, a.y, lx, hx);
            split_pack(a.z, a.w, ly, hy);
            const uint32_t off = SWZ((uint32_t)(r * 128 + c4 * 8));
            *(uint2*)(Asm[0] + off) = make_uint2(lx, ly);
            *(uint2*)(Asm[1] + off) = make_uint2(hx, hy);
        }
#pragma unroll
        for (int t = 0; t < 4; t++) {
            const int idx = tid + t * 128;
            const int r = idx >> 4, c4 = idx & 15;
            const float4 a = __ldg((const float4*)&codes[(size_t)r * 256 + kc * 64 + c4 * 4]);
            uint32_t lx, hx, ly, hy;
            split_pack(a.x, a.y, lx, hx);
            split_pack(a.z, a.w, ly, hy);
            const uint32_t off = SWZ((uint32_t)(r * 128 + c4 * 8));
            *(uint2*)(Bsm[0] + off) = make_uint2(lx, ly);
            *(uint2*)(Bsm[1] + off) = make_uint2(hx, hy);
        }
        __syncthreads();

#pragma unroll
        for (int ks = 0; ks < 4; ks++) {
            const int k0 = ks * 16;
            uint32_t aoff[2], boff[2];
#pragma unroll
            for (int mt = 0; mt < 2; mt++) {
                const int row = w * 32 + mt * 16 + ((g & 1) << 3) + rw;
                aoff[mt] = sbA + SWZ((uint32_t)(row * 128 + (k0 + ((g >> 1) << 3)) * 2));
            }
#pragma unroll
            for (int nt2 = 0; nt2 < 2; nt2++) {
                const int row = nt2 * 16 + ((g >> 1) << 3) + rw;
                boff[nt2] = sbB + SWZ((uint32_t)(row * 128 + (k0 + ((g & 1) << 3)) * 2));
            }
            uint32_t a0[2][4], a1[2][4], b0[2][4], b1[2][4];
#pragma unroll
            for (int mt = 0; mt < 2; mt++) { ldsm4(a0[mt], aoff[mt]); ldsm4(a1[mt], aoff[mt] + 16384); }
#pragma unroll
            for (int nt2 = 0; nt2 < 2; nt2++) { ldsm4(b0[nt2], boff[nt2]); ldsm4(b1[nt2], boff[nt2] + 4096); }
#pragma unroll
            for (int mt = 0; mt < 2; mt++)
#pragma unroll
                for (int nt = 0; nt < 4; nt++) {
                    const int h = nt >> 1, q = (nt & 1) * 2;
                    mma16816(acc[mt][nt], a0[mt], b0[h][q], b0[h][q + 1]);
                    mma16816(acc[mt][nt], a0[mt], b1[h][q], b1[h][q + 1]);
                    mma16816(acc[mt][nt], a1[mt], b0[h][q], b0[h][q + 1]);
                    mma16816(acc[mt][nt], a1[mt], b1[h][q], b1[h][q + 1]);
                }
        }
        __syncthreads();
    }

    const int gid = lane >> 2, tig = lane & 3;
#pragma unroll
    for (int mt = 0; mt < 2; mt++) {
#pragma unroll
        for (int nt = 0; nt < 4; nt++) {
            const int col = nt * 8 + tig * 2;
#pragma unroll
            for (int half = 0; half < 2; half++) {
                const int M = m0 + w * 32 + mt * 16 + gid + half * 8;
                const int b = M / 100, l = M - b * 100;
                float* dst = g_scores + (size_t)b * 3200 + l;
                dst[(size_t)col * 100]       = acc[mt][nt][half * 2];
                dst[(size_t)(col + 1) * 100] = acc[mt][nt][half * 2 + 1];
            }
        }
    }
}

// ---------------------------------------------------------------------------
// K24: per-batch fused  softmax -> interests(mma) -> w(fp32) -> rank -> user(mma).
// One CTA per batch, 256 threads. Interests live entirely in SMEM.
// SMEM layout (dynamic, 1024-aligned base):
//   [0,16K)      Asm: attn splits           | phase5+: cand rows(8K) + partial(8K)
//   [16K,48K)    Bsm: scores, hist splits   | phase5+: wmaskT(8K)@17.5K, wmsm(16K)@25.6K
//   [48K,80K)    ism: interest fp16 splits (swizzled, 4 panels x 2 levels)
//   [80K,112K)   if32: interests fp32 [32][256]
// ---------------------------------------------------------------------------
#define O_ASM   0
#define O_BSM   16384
#define O_ISM   49152
#define O_IF32  81920
#define O_CAND  0
#define O_PART  8192
#define O_WMT   17408
#define O_WMS   25600
#define K24_SMEM (114688 + 1024)

__global__ void __launch_bounds__(256) k24(const float* __restrict__ hist,
                                           const int* __restrict__ numInt,
                                           const float* __restrict__ cand,
                                           const int* __restrict__ catCnt,
                                           float* __restrict__ out) {
    extern __shared__ char raw[];
    const int b = blockIdx.x;
    const int tid = threadIdx.x;
    const int w = tid >> 5;
    const int lane = tid & 31;
    const int g = lane >> 3, rw = lane & 7;
    const int gid = lane >> 2, tig = lane & 3;

    const uint32_t sbr = smem_u32(raw);
    const uint32_t sb = (sbr + 1023u) & ~1023u;
    char* s = raw + (sb - sbr);

    char* Asm = s + O_ASM;
    char* Bsm = s + O_BSM;
    char* ism = s + O_ISM;
    float* if32 = (float*)(s + O_IF32);
    const uint32_t uA = sb + O_ASM, uB = sb + O_BSM, uI = sb + O_ISM;

    // ================= Phase 1: softmax =================
    float* sc = (float*)Bsm;
    {
        const float* src = g_scores + (size_t)b * 3200;
        for (int idx = tid; idx < 3200; idx += 256) sc[idx] = src[idx];
    }
    __syncthreads();
    {
        const int ni = numInt[b];
        for (int k = w; k < 32; k += 8) {
            if (k >= ni) {
                for (int l = lane; l < LEN; l += 32) sc[k * 100 + l] = 0.01f;
            } else {
                float m = -3.4e38f;
                for (int l = lane; l < LEN; l += 32) m = fmaxf(m, sc[k * 100 + l]);
#pragma unroll
                for (int off = 16; off; off >>= 1)
                    m = fmaxf(m, __shfl_xor_sync(0xffffffffu, m, off));
                float ssum = 0.f;
                for (int l = lane; l < LEN; l += 32) {
                    float e = expf(sc[k * 100 + l] - m);
                    sc[k * 100 + l] = e;
                    ssum += e;
                }
#pragma unroll
                for (int off = 16; off; off >>= 1) ssum += __shfl_xor_sync(0xffffffffu, ssum, off);
                for (int l = lane; l < LEN; l += 32) sc[k * 100 + l] = sc[k * 100 + l] / ssum;
            }
        }
    }
    __syncthreads();

    // ================= Phase 2: attn splits -> Asm =================
    for (int idx = tid; idx < 2048; idx += 256) {
        const int k = idx >> 6;
        const int l2 = (idx & 63) * 2;
        const float v0 = (l2 < 100) ? sc[k * 100 + l2] : 0.f;
        const float v1 = (l2 + 1 < 100) ? sc[k * 100 + l2 + 1] : 0.f;
        uint32_t lo, hi;
        split_pack(v0, v1, lo, hi);
        const int h = l2 >> 6, ll = l2 & 63;
        const uint32_t off = SWZ((uint32_t)((h * 32 + k) * 128 + ll * 2));
        *(uint32_t*)(Asm + off)        = lo;
        *(uint32_t*)(Asm + 8192 + off) = hi;
    }
    __syncthreads();

    // ================= Phase 3: interests mma (8-warp, 4-pass) =================
    const int pnl = w >> 1;
    const int sub = w & 1;
    float acc[2][2][2][4];
#pragma unroll
    for (int mt = 0; mt < 2; mt++)
#pragma unroll
        for (int ntt = 0; ntt < 2; ntt++)
#pragma unroll
            for (int n8 = 0; n8 < 2; n8++)
#pragma unroll
                for (int i = 0; i < 4; i++) acc[mt][ntt][n8][i] = 0.f;

    const float* Hb = hist + (size_t)b * LEN * DIM;
    for (int ch = 0; ch < 4; ch++) {
        const int l0 = ch * 32;
#pragma unroll
        for (int t = 0; t < 8; t++) {
            const int idx = tid + t * 256;
            const int lr = idx >> 6, c4 = idx & 63;
            const int l = l0 + lr;
            float4 a = make_float4(0.f, 0.f, 0.f, 0.f);
            if (l < LEN) a = __ldg((const float4*)&Hb[(size_t)l * 256 + c4 * 4]);
            uint32_t lx, hx, ly, hy;
            split_pack(a.x, a.y, lx, hx);
            split_pack(a.z, a.w, ly, hy);
            const int d = c4 * 4;
            const int p = d >> 6, dcol = d & 63;
            const uint32_t off = p * 4096 + SWZ((uint32_t)(lr * 128 + dcol * 2));
            *(uint2*)(Bsm + off)         = make_uint2(lx, ly);
            *(uint2*)(Bsm + 16384 + off) = make_uint2(hx, hy);
        }
        __syncthreads();

#pragma unroll
        for (int ks2 = 0; ks2 < 2; ks2++) {
            const int kk = l0 + ks2 * 16;
            const int half = kk >> 6, lloc = kk & 63;

            uint32_t a0[2][4], a1[2][4];
#pragma unroll
            for (int mt = 0; mt < 2; mt++) {
                const int row = mt * 16 + ((g & 1) << 3) + rw;
                const uint32_t ao = SWZ((uint32_t)((half * 32 + row) * 128 + (lloc + ((g >> 1) << 3)) * 2));
                ldsm4(a0[mt], uA + ao);
                ldsm4(a1[mt], uA + 8192 + ao);
            }

            const int trow = ks2 * 16 + (lane & 7) + ((lane >> 3) & 1) * 8;
            const int tcolb = ((lane >> 4) & 1) * 8;
#pragma unroll
            for (int ntt = 0; ntt < 2; ntt++) {
                const int ntg = sub * 2 + ntt;
                const uint32_t bo = pnl * 4096 + SWZ((uint32_t)(trow * 128 + (ntg * 16 + tcolb) * 2));
                uint32_t bl0[4], bl1[4];
                ldsm4t(bl0, uB + bo);
                ldsm4t(bl1, uB + 16384 + bo);
#pragma unroll
                for (int mt = 0; mt < 2; mt++) {
                    float* c0 = acc[mt][ntt][0];
                    float* c1 = acc[mt][ntt][1];
                    mma16816(c0, a0[mt], bl0[0], bl0[1]);
                    mma16816(c0, a0[mt], bl1[0], bl1[1]);
                    mma16816(c0, a1[mt], bl0[0], bl0[1]);
                    mma16816(c0, a1[mt], bl1[0], bl1[1]);
                    mma16816(c1, a0[mt], bl0[2], bl0[3]);
                    mma16816(c1, a0[mt], bl1[2], bl1[3]);
                    mma16816(c1, a1[mt], bl0[2], bl0[3]);
                    mma16816(c1, a1[mt], bl1[2], bl1[3]);
                }
            }
        }
        __syncthreads();
    }

    // ================= Phase 4: interests -> if32 + ism splits =================
#pragma unroll
    for (int mt = 0; mt < 2; mt++) {
#pragma unroll
        for (int ntt = 0; ntt < 2; ntt++) {
            const int ntg = sub * 2 + ntt;
#pragma unroll
            for (int n8 = 0; n8 < 2; n8++) {
                const int d = pnl * 64 + ntg * 16 + n8 * 8 + tig * 2;
#pragma unroll
                for (int hh = 0; hh < 2; hh++) {
                    const int kk = mt * 16 + gid + hh * 8;
                    const float vx = acc[mt][ntt][n8][hh * 2], vy = acc[mt][ntt][n8][hh * 2 + 1];
                    *(float2*)&if32[kk * 256 + d] = make_float2(vx, vy);
                    uint32_t lo, hi;
                    split_pack(vx, vy, lo, hi);
                    const int dloc = d & 63;
                    const uint32_t off = pnl * 4096 + SWZ((uint32_t)(kk * 128 + dloc * 2));
                    *(uint32_t*)(ism + off)         = lo;
                    *(uint32_t*)(ism + 16384 + off) = hi;
                }
            }
        }
    }
    __syncthreads();

    // ================= Phase 5: w-GEMM (exact fp32) + rank, 64 cands =================
    float* cand_sm = (float*)(s + O_CAND);
    float* partial = (float*)(s + O_PART);
    float* wmaskT  = (float*)(s + O_WMT);
    char*  wmsm    = s + O_WMS;
    const uint32_t uW = sb + O_WMS;

    u64 ireg2[16];
    {
        const u64* ibase = (const u64*)(if32 + lane * 256 + w * 32);
#pragma unroll
        for (int j = 0; j < 16; j++) ireg2[j] = ibase[j];
    }

    const int cc = catCnt[b];
    int dynK = (int)ceilf(log2f(8.0f * (float)cc));
    dynK = dynK < 1 ? 1 : (dynK > 32 ? 32 : dynK);

    const float* Cb = cand + (size_t)b * NCAND * DIM;
    for (int n0 = 0; n0 < 64; n0 += 8) {
        const float4* src = (const float4*)(Cb + (size_t)n0 * DIM);
        float4* dst = (float4*)cand_sm;
        dst[tid] = src[tid];
        dst[tid + 256] = src[tid + 256];
        __syncthreads();

        u64 p[8];
#pragma unroll
        for (int r = 0; r < 8; r++) p[r] = 0ull;
        const uint4* rbase4 = (const uint4*)cand_sm;
#pragma unroll
        for (int j4 = 0; j4 < 8; j4++) {
            const u64 iv0 = ireg2[j4 * 2], iv1 = ireg2[j4 * 2 + 1];
            const int coff = w * 8 + j4;
#pragma unroll
            for (int r = 0; r < 8; r++) {
                const uint4 v = rbase4[r * 64 + coff];
                p[r] = ffma2(iv0, packu(v.x, v.y), p[r]);
                p[r] = ffma2(iv1, packu(v.z, v.w), p[r]);
            }
        }
#pragma unroll
        for (int r = 0; r < 8; r++) {
            float2 t = unpack2(p[r]);
            partial[w * 256 + r * 32 + lane] = t.x + t.y;
        }
        __syncthreads();

        // reduce: thread (r=tid>>5 == warp, k=lane) -> row n0+r
        {
            const int k = lane, r = w;
            float ssum = 0.f;
#pragma unroll
            for (int ww = 0; ww < 8; ww++) ssum += partial[ww * 256 + r * 32 + k];
            wmaskT[(n0 + r) * 32 + k] = ssum;
        }
        __syncwarp();

        // rank: warp w owns row n0+w (it just wrote it)
        {
            const float wi = wmaskT[(n0 + w) * 32 + lane];
            int rank = 0;
#pragma unroll
            for (int j = 0; j < 32; j++) {
                const float wj = __shfl_sync(0xffffffffu, wi, j);
                rank += (wj > wi) || (wj == wi && j < lane);
            }
            wmaskT[(n0 + w) * 32 + lane] = (rank < dynK) ? wi : 0.f;
        }
        __syncthreads();
    }

    // ================= Phase 6: wmask fp16 splits =================
    for (int idx = tid; idx < 2048; idx += 256) {
        const int r = idx >> 5, c = idx & 31;
        const float v = wmaskT[r * 32 + c];
        const __half m1 = __float2half_rn(v);
        const __half m2 = __float2half_rn(v - __half2float(m1));
        const uint32_t off = SWZ((uint32_t)(r * 128 + c * 2));
        *(__half*)(wmsm + off)        = m1;
        *(__half*)(wmsm + 8192 + off) = m2;
    }
    __syncthreads();

    // ================= Phase 7: user mma (3-pass) =================
    const int mt = w & 3;            // cand 16-tile 0..3 (64 cands)
    const int phh = w >> 2;          // d-half 0..1

    float* Ob = out + (size_t)b * NCAND * DIM;
#pragma unroll
    for (int pp = 0; pp < 2; pp++) {
        const int pn = phh * 2 + pp;   // panel 0..3

        float ua[4][2][4];
#pragma unroll
        for (int ntt = 0; ntt < 4; ntt++)
#pragma unroll
            for (int n8 = 0; n8 < 2; n8++)
#pragma unroll
                for (int i = 0; i < 4; i++) ua[ntt][n8][i] = 0.f;

#pragma unroll
        for (int ks = 0; ks < 2; ks++) {
            const int arow = mt * 16 + ((g & 1) << 3) + rw;
            const int acol = ks * 16 + ((g >> 1) << 3);
            const uint32_t ao = SWZ((uint32_t)(arow * 128 + acol * 2));
            uint32_t am1[4], am2[4];
            ldsm4(am1, uW + ao);
            ldsm4(am2, uW + 8192 + ao);

            const int trow = ks * 16 + (lane & 7) + ((lane >> 3) & 1) * 8;
            const int tcolb = ((lane >> 4) & 1) * 8;
#pragma unroll
            for (int ntt = 0; ntt < 4; ntt++) {
                const uint32_t bo = pn * 4096 + SWZ((uint32_t)(trow * 128 + (ntt * 16 + tcolb) * 2));
                uint32_t bi1[4], bi2[4];
                ldsm4t(bi1, uI + bo);
                ldsm4t(bi2, uI + 16384 + bo);
#pragma unroll
                for (int n8 = 0; n8 < 2; n8++) {
                    float* c = ua[ntt][n8];
                    mma16816(c, am1, bi1[n8 * 2], bi1[n8 * 2 + 1]);
                    mma16816(c, am1, bi2[n8 * 2], bi2[n8 * 2 + 1]);
                    mma16816(c, am2, bi1[n8 * 2], bi1[n8 * 2 + 1]);
                }
            }
        }

#pragma unroll
        for (int ntt = 0; ntt < 4; ntt++) {
#pragma unroll
            for (int n8 = 0; n8 < 2; n8++) {
                const int d = pn * 64 + ntt * 16 + n8 * 8 + tig * 2;
                const int r0 = mt * 16 + gid;
                *(float2*)&Ob[(size_t)r0 * 256 + d]       = make_float2(ua[ntt][n8][0], ua[ntt][n8][1]);
                *(float2*)&Ob[(size_t)(r0 + 8) * 256 + d] = make_float2(ua[ntt][n8][2], ua[ntt][n8][3]);
            }
        }
    }
}

// ---------------------------------------------------------------------------
extern "C" void kernel_launch(void* const* d_in, const int* in_sizes, int n_in,
                              void* d_out, int out_size) {
    (void)in_sizes; (void)n_in; (void)out_size;
    const float* hist  = (const float*)d_in[0];
    const float* cand  = (const float*)d_in[2];
    const int*   numI  = (const int*)d_in[3];
    const int*   catC  = (const int*)d_in[4];
    const float* W     = (const float*)d_in[5];
    const float* codes = (const float*)d_in[6];
    float* out = (float*)d_out;

    static bool attr_set = false;
    if (!attr_set) {
        cudaFuncSetAttribute(k1_mma, cudaFuncAttributeMaxDynamicSharedMemorySize, K1_SMEM);
        cudaFuncSetAttribute(k24, cudaFuncAttributeMaxDynamicSharedMemorySize, K24_SMEM);
        attr_set = true;
    }

    kw_split<<<256, 256>>>(W);
    k1_mma<<<dim3(2, 400), 256, K1_SMEM>>>(hist);
    k2a_kernel<<<400, 128>>>(codes);
    k24<<<BSZ, 256, K24_SMEM>>>(hist, numI, cand, catC, out);
}

// round 13
// speedup vs baseline: 1.2111x; 1.0184x over previous
#include <cuda_runtime.h>
#include <cuda_fp16.h>
#include <math.h>
#include <stdint.h>

#define BSZ   512
#define LEN   100
#define NCAND 64
#define DIM   256
#define KIN   32

typedef unsigned long long u64;

// Scratch (no allocations allowed)
__device__ float  g_proj[BSZ * LEN * DIM];          // 52.4 MB
__device__ float  g_scores[BSZ * KIN * LEN];        // [b][k][l]
__device__ __half g_h1[256 * 256];                  // W splits
__device__ __half g_h2[256 * 256];

// ---- packed fp32x2 helpers --------------------------------------------------
__device__ __forceinline__ u64 ffma2(u64 a, u64 b, u64 c) {
    u64 d;
    asm("fma.rn.f32x2 %0, %1, %2, %3;" : "=l"(d) : "l"(a), "l"(b), "l"(c));
    return d;
}
__device__ __forceinline__ u64 packu(uint32_t a, uint32_t b) {
    u64 r;
    asm("mov.b64 %0, {%1, %2};" : "=l"(r) : "r"(a), "r"(b));
    return r;
}
__device__ __forceinline__ float2 unpack2(u64 v) {
    float2 r;
    asm("mov.b64 {%0, %1}, %2;" : "=f"(r.x), "=f"(r.y) : "l"(v));
    return r;
}

// ---- mma.sync helpers ---------------------------------------------------------
__device__ __forceinline__ uint32_t smem_u32(const void* p) {
    uint32_t a;
    asm("{ .reg .u64 t; cvta.to.shared.u64 t, %1; cvt.u32.u64 %0, t; }" : "=r"(a) : "l"(p));
    return a;
}
__device__ __forceinline__ void ldsm4(uint32_t* r, uint32_t addr) {
    asm volatile("ldmatrix.sync.aligned.m8n8.x4.shared.b16 {%0,%1,%2,%3}, [%4];"
                 : "=r"(r[0]), "=r"(r[1]), "=r"(r[2]), "=r"(r[3]) : "r"(addr) : "memory");
}
__device__ __forceinline__ void ldsm4t(uint32_t* r, uint32_t addr) {
    asm volatile("ldmatrix.sync.aligned.m8n8.x4.trans.shared.b16 {%0,%1,%2,%3}, [%4];"
                 : "=r"(r[0]), "=r"(r[1]), "=r"(r[2]), "=r"(r[3]) : "r"(addr) : "memory");
}
__device__ __forceinline__ void mma16816(float* d, const uint32_t* a, uint32_t b0, uint32_t b1) {
    asm volatile("mma.sync.aligned.m16n8k16.row.col.f32.f16.f16.f32 "
                 "{%0,%1,%2,%3}, {%4,%5,%6,%7}, {%8,%9}, {%0,%1,%2,%3};"
                 : "+f"(d[0]), "+f"(d[1]), "+f"(d[2]), "+f"(d[3])
                 : "r"(a[0]), "r"(a[1]), "r"(a[2]), "r"(a[3]), "r"(b0), "r"(b1));
}

#define SWZ(o) ((o) ^ (((o) >> 3) & 0x70))

__device__ __forceinline__ uint32_t h2_u32(__half a, __half b) {
    __half2 t(a, b);
    return *reinterpret_cast<uint32_t*>(&t);
}
__device__ __forceinline__ void split_pack(float x, float y, uint32_t& lo, uint32_t& hi) {
    const __half ax = __float2half_rn(x), ay = __float2half_rn(y);
    const __half bx = __float2half_rn(x - __half2float(ax));
    const __half by = __float2half_rn(y - __half2float(ay));
    lo = h2_u32(ax, ay);
    hi = h2_u32(bx, by);
}

// ---------------------------------------------------------------------------
// W split
// ---------------------------------------------------------------------------
__global__ void kw_split(const float* __restrict__ W) {
    const int i = blockIdx.x * 256 + threadIdx.x;
    const float a = W[i];
    const __half h1 = __float2half_rn(a);
    g_h1[i] = h1;
    g_h2[i] = __float2half_rn(a - __half2float(h1));
}

// ---------------------------------------------------------------------------
// K1: proj = tanh(hist @ W^T) via mma.sync fp16, 2-level split (3 passes).
// ---------------------------------------------------------------------------
#define A_OFF  0
#define B_OFF  32768
#define LVL    16384
#define K1_SMEM (65536 + 1024)

__global__ void __launch_bounds__(256, 2) k1_mma(const float* __restrict__ hist) {
    extern __shared__ char smem_raw[];
    const int tid = threadIdx.x;
    const int wid = tid >> 5;
    const int lane = tid & 31;
    const int warp_m = wid >> 2;
    const int warp_n = wid & 3;
    const int m0 = blockIdx.y * 128;
    const int n0 = blockIdx.x * 128;

    const uint32_t sb_raw = smem_u32(smem_raw);
    const uint32_t sb = (sb_raw + 1023u) & ~1023u;
    char* smem = smem_raw + (sb - sb_raw);

    const int g  = lane >> 3;
    const int rw = lane & 7;

    float acc[4][4][4];
#pragma unroll
    for (int mt = 0; mt < 4; mt++)
#pragma unroll
        for (int nt = 0; nt < 4; nt++)
#pragma unroll
            for (int i = 0; i < 4; i++) acc[mt][nt][i] = 0.f;

    for (int kc = 0; kc < 4; kc++) {
#pragma unroll
        for (int t = 0; t < 8; t++) {
            const int idx = tid + t * 256;
            const int r = idx >> 4, c4 = idx & 15;
            const float4 a = __ldg((const float4*)&hist[(size_t)(m0 + r) * 256 + kc * 64 + c4 * 4]);
            uint32_t lx, hx, ly, hy;
            split_pack(a.x, a.y, lx, hx);
            split_pack(a.z, a.w, ly, hy);
            const uint32_t off = SWZ((uint32_t)(r * 128 + c4 * 8));
            *(uint2*)(smem + A_OFF + off)       = make_uint2(lx, ly);
            *(uint2*)(smem + A_OFF + LVL + off) = make_uint2(hx, hy);
        }
        {
            const __half* gw[2] = {g_h1, g_h2};
#pragma unroll
            for (int lv = 0; lv < 2; lv++) {
#pragma unroll
                for (int t = 0; t < 4; t++) {
                    const int idx = tid + t * 256;
                    const int n = idx >> 3, u = idx & 7;
                    const uint4 v = *(const uint4*)&gw[lv][(size_t)(n0 + n) * 256 + kc * 64 + u * 8];
                    *(uint4*)(smem + B_OFF + lv * LVL + SWZ((uint32_t)(n * 128 + u * 16))) = v;
                }
            }
        }
        __syncthreads();

#pragma unroll
        for (int ks = 0; ks < 4; ks++) {
            const int k0 = ks * 16;
            uint32_t aoff[4], boff[2];
#pragma unroll
            for (int mt = 0; mt < 4; mt++) {
                const int row = warp_m * 64 + mt * 16 + ((g & 1) << 3) + rw;
                const int kk  = k0 + ((g >> 1) << 3);
                aoff[mt] = sb + A_OFF + SWZ((uint32_t)(row * 128 + kk * 2));
            }
#pragma unroll
            for (int nt2 = 0; nt2 < 2; nt2++) {
                const int row = warp_n * 32 + nt2 * 16 + ((g >> 1) << 3) + rw;
                const int kk  = k0 + ((g & 1) << 3);
                boff[nt2] = sb + B_OFF + SWZ((uint32_t)(row * 128 + kk * 2));
            }

            uint32_t a0[4][4], a1[4][4], b0[2][4], b1[2][4];
#pragma unroll
            for (int mt = 0; mt < 4; mt++) { ldsm4(a0[mt], aoff[mt]); ldsm4(a1[mt], aoff[mt] + LVL); }
#pragma unroll
            for (int nt2 = 0; nt2 < 2; nt2++) { ldsm4(b0[nt2], boff[nt2]); ldsm4(b1[nt2], boff[nt2] + LVL); }

#pragma unroll
            for (int mt = 0; mt < 4; mt++)
#pragma unroll
                for (int nt = 0; nt < 4; nt++) {
                    const int h = nt >> 1, q = (nt & 1) * 2;
                    mma16816(acc[mt][nt], a0[mt], b0[h][q], b0[h][q + 1]);
                    mma16816(acc[mt][nt], a0[mt], b1[h][q], b1[h][q + 1]);
                    mma16816(acc[mt][nt], a1[mt], b0[h][q], b0[h][q + 1]);
                }
        }
        __syncthreads();
    }

    const int gid = lane >> 2, tig = lane & 3;
#pragma unroll
    for (int mt = 0; mt < 4; mt++) {
#pragma unroll
        for (int nt = 0; nt < 4; nt++) {
            const int row = m0 + warp_m * 64 + mt * 16 + gid;
            const int col = n0 + warp_n * 32 + nt * 8 + tig * 2;
            float2 v0, v1;
            v0.x = tanhf(acc[mt][nt][0]); v0.y = tanhf(acc[mt][nt][1]);
            v1.x = tanhf(acc[mt][nt][2]); v1.y = tanhf(acc[mt][nt][3]);
            *(float2*)&g_proj[(size_t)row * 256 + col]       = v0;
            *(float2*)&g_proj[(size_t)(row + 8) * 256 + col] = v1;
        }
    }
}

// ---------------------------------------------------------------------------
// K2a: scores = g_proj @ codes^T  (R10 version)
// ---------------------------------------------------------------------------
__global__ void __launch_bounds__(128) k2a_kernel(const float* __restrict__ codes) {
    __shared__ __align__(16) char Asm[2][16384];
    __shared__ __align__(16) char Bsm[2][4096];

    const int tid = threadIdx.x;
    const int w = tid >> 5;
    const int lane = tid & 31;
    const int m0 = blockIdx.x * 128;
    const int g = lane >> 3, rw = lane & 7;
    const uint32_t sbA = smem_u32(Asm);
    const uint32_t sbB = smem_u32(Bsm);

    float acc[2][4][4];
#pragma unroll
    for (int mt = 0; mt < 2; mt++)
#pragma unroll
        for (int nt = 0; nt < 4; nt++)
#pragma unroll
            for (int i = 0; i < 4; i++) acc[mt][nt][i] = 0.f;

    for (int kc = 0; kc < 4; kc++) {
#pragma unroll
        for (int t = 0; t < 16; t++) {
            const int idx = tid + t * 128;
            const int r = idx >> 4, c4 = idx & 15;
            const float4 a = __ldg((const float4*)&g_proj[(size_t)(m0 + r) * 256 + kc * 64 + c4 * 4]);
            uint32_t lx, hx, ly, hy;
            split_pack(a.x, a.y, lx, hx);
            split_pack(a.z, a.w, ly, hy);
            const uint32_t off = SWZ((uint32_t)(r * 128 + c4 * 8));
            *(uint2*)(Asm[0] + off) = make_uint2(lx, ly);
            *(uint2*)(Asm[1] + off) = make_uint2(hx, hy);
        }
#pragma unroll
        for (int t = 0; t < 4; t++) {
            const int idx = tid + t * 128;
            const int r = idx >> 4, c4 = idx & 15;
            const float4 a = __ldg((const float4*)&codes[(size_t)r * 256 + kc * 64 + c4 * 4]);
            uint32_t lx, hx, ly, hy;
            split_pack(a.x, a.y, lx, hx);
            split_pack(a.z, a.w, ly, hy);
            const uint32_t off = SWZ((uint32_t)(r * 128 + c4 * 8));
            *(uint2*)(Bsm[0] + off) = make_uint2(lx, ly);
            *(uint2*)(Bsm[1] + off) = make_uint2(hx, hy);
        }
        __syncthreads();

#pragma unroll
        for (int ks = 0; ks < 4; ks++) {
            const int k0 = ks * 16;
            uint32_t aoff[2], boff[2];
#pragma unroll
            for (int mt = 0; mt < 2; mt++) {
                const int row = w * 32 + mt * 16 + ((g & 1) << 3) + rw;
                aoff[mt] = sbA + SWZ((uint32_t)(row * 128 + (k0 + ((g >> 1) << 3)) * 2));
            }
#pragma unroll
            for (int nt2 = 0; nt2 < 2; nt2++) {
                const int row = nt2 * 16 + ((g >> 1) << 3) + rw;
                boff[nt2] = sbB + SWZ((uint32_t)(row * 128 + (k0 + ((g & 1) << 3)) * 2));
            }
            uint32_t a0[2][4], a1[2][4], b0[2][4], b1[2][4];
#pragma unroll
            for (int mt = 0; mt < 2; mt++) { ldsm4(a0[mt], aoff[mt]); ldsm4(a1[mt], aoff[mt] + 16384); }
#pragma unroll
            for (int nt2 = 0; nt2 < 2; nt2++) { ldsm4(b0[nt2], boff[nt2]); ldsm4(b1[nt2], boff[nt2] + 4096); }
#pragma unroll
            for (int mt = 0; mt < 2; mt++)
#pragma unroll
                for (int nt = 0; nt < 4; nt++) {
                    const int h = nt >> 1, q = (nt & 1) * 2;
                    mma16816(acc[mt][nt], a0[mt], b0[h][q], b0[h][q + 1]);
                    mma16816(acc[mt][nt], a0[mt], b1[h][q], b1[h][q + 1]);
                    mma16816(acc[mt][nt], a1[mt], b0[h][q], b0[h][q + 1]);
                    mma16816(acc[mt][nt], a1[mt], b1[h][q], b1[h][q + 1]);
                }
        }
        __syncthreads();
    }

    const int gid = lane >> 2, tig = lane & 3;
#pragma unroll
    for (int mt = 0; mt < 2; mt++) {
#pragma unroll
        for (int nt = 0; nt < 4; nt++) {
            const int col = nt * 8 + tig * 2;
#pragma unroll
            for (int half = 0; half < 2; half++) {
                const int M = m0 + w * 32 + mt * 16 + gid + half * 8;
                const int b = M / 100, l = M - b * 100;
                float* dst = g_scores + (size_t)b * 3200 + l;
                dst[(size_t)col * 100]       = acc[mt][nt][half * 2];
                dst[(size_t)(col + 1) * 100] = acc[mt][nt][half * 2 + 1];
            }
        }
    }
}

// ---------------------------------------------------------------------------
// K24: per-batch fused  softmax -> interests(mma) -> w(fp32) -> rank -> user(mma).
// COMPACTED SMEM (80KB) -> 2 CTAs/SM.
// Liveness-based layout (dynamic, 1024-aligned base):
//   phases 1-3: Asm attn splits [0,16K) | Bsm scores/hist splits [16K,48K)
//   phase 4:    if32 fp32 interests [0,32K)  (Asm/Bsm dead)
//   phase 5-6:  cand[0,8K) partial[8K,16K) wmaskT[16K,24K) wmsm[24K,40K)
//               (if32 dead after ireg2 register load + sync)
//   phases 4-7: ism interest fp16 splits [48K,80K)
// ---------------------------------------------------------------------------
#define O_ASM   0
#define O_BSM   16384
#define O_IF32  0
#define O_CAND  0
#define O_PART  8192
#define O_WMT   16384
#define O_WMS   24576
#define O_ISM   49152
#define K24_SMEM (81920 + 1024)

__global__ void __launch_bounds__(256, 2) k24(const float* __restrict__ hist,
                                              const int* __restrict__ numInt,
                                              const float* __restrict__ cand,
                                              const int* __restrict__ catCnt,
                                              float* __restrict__ out) {
    extern __shared__ char raw[];
    const int b = blockIdx.x;
    const int tid = threadIdx.x;
    const int w = tid >> 5;
    const int lane = tid & 31;
    const int g = lane >> 3, rw = lane & 7;
    const int gid = lane >> 2, tig = lane & 3;

    const uint32_t sbr = smem_u32(raw);
    const uint32_t sb = (sbr + 1023u) & ~1023u;
    char* s = raw + (sb - sbr);

    char* Asm = s + O_ASM;
    char* Bsm = s + O_BSM;
    char* ism = s + O_ISM;
    float* if32 = (float*)(s + O_IF32);
    const uint32_t uA = sb + O_ASM, uB = sb + O_BSM, uI = sb + O_ISM;

    // ================= Phase 1: softmax (sc overlays Bsm) =================
    float* sc = (float*)Bsm;
    {
        const float* src = g_scores + (size_t)b * 3200;
        for (int idx = tid; idx < 3200; idx += 256) sc[idx] = src[idx];
    }
    __syncthreads();
    {
        const int ni = numInt[b];
        for (int k = w; k < 32; k += 8) {
            if (k >= ni) {
                for (int l = lane; l < LEN; l += 32) sc[k * 100 + l] = 0.01f;
            } else {
                float m = -3.4e38f;
                for (int l = lane; l < LEN; l += 32) m = fmaxf(m, sc[k * 100 + l]);
#pragma unroll
                for (int off = 16; off; off >>= 1)
                    m = fmaxf(m, __shfl_xor_sync(0xffffffffu, m, off));
                float ssum = 0.f;
                for (int l = lane; l < LEN; l += 32) {
                    float e = expf(sc[k * 100 + l] - m);
                    sc[k * 100 + l] = e;
                    ssum += e;
                }
#pragma unroll
                for (int off = 16; off; off >>= 1) ssum += __shfl_xor_sync(0xffffffffu, ssum, off);
                for (int l = lane; l < LEN; l += 32) sc[k * 100 + l] = sc[k * 100 + l] / ssum;
            }
        }
    }
    __syncthreads();

    // ================= Phase 2: attn splits -> Asm =================
    for (int idx = tid; idx < 2048; idx += 256) {
        const int k = idx >> 6;
        const int l2 = (idx & 63) * 2;
        const float v0 = (l2 < 100) ? sc[k * 100 + l2] : 0.f;
        const float v1 = (l2 + 1 < 100) ? sc[k * 100 + l2 + 1] : 0.f;
        uint32_t lo, hi;
        split_pack(v0, v1, lo, hi);
        const int h = l2 >> 6, ll = l2 & 63;
        const uint32_t off = SWZ((uint32_t)((h * 32 + k) * 128 + ll * 2));
        *(uint32_t*)(Asm + off)        = lo;
        *(uint32_t*)(Asm + 8192 + off) = hi;
    }
    __syncthreads();

    // ================= Phase 3: interests mma (8-warp, 4-pass) =================
    const int pnl = w >> 1;
    const int sub = w & 1;
    float acc[2][2][2][4];
#pragma unroll
    for (int mt = 0; mt < 2; mt++)
#pragma unroll
        for (int ntt = 0; ntt < 2; ntt++)
#pragma unroll
            for (int n8 = 0; n8 < 2; n8++)
#pragma unroll
                for (int i = 0; i < 4; i++) acc[mt][ntt][n8][i] = 0.f;

    const float* Hb = hist + (size_t)b * LEN * DIM;
    for (int ch = 0; ch < 4; ch++) {
        const int l0 = ch * 32;
#pragma unroll
        for (int t = 0; t < 8; t++) {
            const int idx = tid + t * 256;
            const int lr = idx >> 6, c4 = idx & 63;
            const int l = l0 + lr;
            float4 a = make_float4(0.f, 0.f, 0.f, 0.f);
            if (l < LEN) a = __ldg((const float4*)&Hb[(size_t)l * 256 + c4 * 4]);
            uint32_t lx, hx, ly, hy;
            split_pack(a.x, a.y, lx, hx);
            split_pack(a.z, a.w, ly, hy);
            const int d = c4 * 4;
            const int p = d >> 6, dcol = d & 63;
            const uint32_t off = p * 4096 + SWZ((uint32_t)(lr * 128 + dcol * 2));
            *(uint2*)(Bsm + off)         = make_uint2(lx, ly);
            *(uint2*)(Bsm + 16384 + off) = make_uint2(hx, hy);
        }
        __syncthreads();

#pragma unroll
        for (int ks2 = 0; ks2 < 2; ks2++) {
            const int kk = l0 + ks2 * 16;
            const int half = kk >> 6, lloc = kk & 63;

            uint32_t a0[2][4], a1[2][4];
#pragma unroll
            for (int mt = 0; mt < 2; mt++) {
                const int row = mt * 16 + ((g & 1) << 3) + rw;
                const uint32_t ao = SWZ((uint32_t)((half * 32 + row) * 128 + (lloc + ((g >> 1) << 3)) * 2));
                ldsm4(a0[mt], uA + ao);
                ldsm4(a1[mt], uA + 8192 + ao);
            }

            const int trow = ks2 * 16 + (lane & 7) + ((lane >> 3) & 1) * 8;
            const int tcolb = ((lane >> 4) & 1) * 8;
#pragma unroll
            for (int ntt = 0; ntt < 2; ntt++) {
                const int ntg = sub * 2 + ntt;
                const uint32_t bo = pnl * 4096 + SWZ((uint32_t)(trow * 128 + (ntg * 16 + tcolb) * 2));
                uint32_t bl0[4], bl1[4];
                ldsm4t(bl0, uB + bo);
                ldsm4t(bl1, uB + 16384 + bo);
#pragma unroll
                for (int mt = 0; mt < 2; mt++) {
                    float* c0 = acc[mt][ntt][0];
                    float* c1 = acc[mt][ntt][1];
                    mma16816(c0, a0[mt], bl0[0], bl0[1]);
                    mma16816(c0, a0[mt], bl1[0], bl1[1]);
                    mma16816(c0, a1[mt], bl0[0], bl0[1]);
                    mma16816(c0, a1[mt], bl1[0], bl1[1]);
                    mma16816(c1, a0[mt], bl0[2], bl0[3]);
                    mma16816(c1, a0[mt], bl1[2], bl1[3]);
                    mma16816(c1, a1[mt], bl0[2], bl0[3]);
                    mma16816(c1, a1[mt], bl1[2], bl1[3]);
                }
            }
        }
        __syncthreads();
    }

    // ================= Phase 4: interests -> if32 (overlays Asm/Bsm) + ism =====
#pragma unroll
    for (int mt = 0; mt < 2; mt++) {
#pragma unroll
        for (int ntt = 0; ntt < 2; ntt++) {
            const int ntg = sub * 2 + ntt;
#pragma unroll
            for (int n8 = 0; n8 < 2; n8++) {
                const int d = pnl * 64 + ntg * 16 + n8 * 8 + tig * 2;
#pragma unroll
                for (int hh = 0; hh < 2; hh++) {
                    const int kk = mt * 16 + gid + hh * 8;
                    const float vx = acc[mt][ntt][n8][hh * 2], vy = acc[mt][ntt][n8][hh * 2 + 1];
                    *(float2*)&if32[kk * 256 + d] = make_float2(vx, vy);
                    uint32_t lo, hi;
                    split_pack(vx, vy, lo, hi);
                    const int dloc = d & 63;
                    const uint32_t off = pnl * 4096 + SWZ((uint32_t)(kk * 128 + dloc * 2));
                    *(uint32_t*)(ism + off)         = lo;
                    *(uint32_t*)(ism + 16384 + off) = hi;
                }
            }
        }
    }
    __syncthreads();

    // ================= Phase 5: w-GEMM (exact fp32) + rank, 64 cands ==========
    float* cand_sm = (float*)(s + O_CAND);
    float* partial = (float*)(s + O_PART);
    float* wmaskT  = (float*)(s + O_WMT);
    char*  wmsm    = s + O_WMS;
    const uint32_t uW = sb + O_WMS;

    u64 ireg2[16];
    {
        const u64* ibase = (const u64*)(if32 + lane * 256 + w * 32);
#pragma unroll
        for (int j = 0; j < 16; j++) ireg2[j] = ibase[j];
    }
    __syncthreads();   // if32 dead after this; cand_sm overlays it

    const int cc = catCnt[b];
    int dynK = (int)ceilf(log2f(8.0f * (float)cc));
    dynK = dynK < 1 ? 1 : (dynK > 32 ? 32 : dynK);

    const float* Cb = cand + (size_t)b * NCAND * DIM;
    for (int n0 = 0; n0 < 64; n0 += 8) {
        const float4* src = (const float4*)(Cb + (size_t)n0 * DIM);
        float4* dst = (float4*)cand_sm;
        dst[tid] = src[tid];
        dst[tid + 256] = src[tid + 256];
        __syncthreads();

        u64 p[8];
#pragma unroll
        for (int r = 0; r < 8; r++) p[r] = 0ull;
        const uint4* rbase4 = (const uint4*)cand_sm;
#pragma unroll
        for (int j4 = 0; j4 < 8; j4++) {
            const u64 iv0 = ireg2[j4 * 2], iv1 = ireg2[j4 * 2 + 1];
            const int coff = w * 8 + j4;
#pragma unroll
            for (int r = 0; r < 8; r++) {
                const uint4 v = rbase4[r * 64 + coff];
                p[r] = ffma2(iv0, packu(v.x, v.y), p[r]);
                p[r] = ffma2(iv1, packu(v.z, v.w), p[r]);
            }
        }
#pragma unroll
        for (int r = 0; r < 8; r++) {
            float2 t = unpack2(p[r]);
            partial[w * 256 + r * 32 + lane] = t.x + t.y;
        }
        __syncthreads();

        {
            const int k = lane, r = w;
            float ssum = 0.f;
#pragma unroll
            for (int ww = 0; ww < 8; ww++) ssum += partial[ww * 256 + r * 32 + k];
            wmaskT[(n0 + r) * 32 + k] = ssum;
        }
        __syncwarp();

        {
            const float wi = wmaskT[(n0 + w) * 32 + lane];
            int rank = 0;
#pragma unroll
            for (int j = 0; j < 32; j++) {
                const float wj = __shfl_sync(0xffffffffu, wi, j);
                rank += (wj > wi) || (wj == wi && j < lane);
            }
            wmaskT[(n0 + w) * 32 + lane] = (rank < dynK) ? wi : 0.f;
        }
        __syncthreads();
    }

    // ================= Phase 6: wmask fp16 splits =================
    for (int idx = tid; idx < 2048; idx += 256) {
        const int r = idx >> 5, c = idx & 31;
        const float v = wmaskT[r * 32 + c];
        const __half m1 = __float2half_rn(v);
        const __half m2 = __float2half_rn(v - __half2float(m1));
        const uint32_t off = SWZ((uint32_t)(r * 128 + c * 2));
        *(__half*)(wmsm + off)        = m1;
        *(__half*)(wmsm + 8192 + off) = m2;
    }
    __syncthreads();

    // ================= Phase 7: user mma (3-pass) =================
    const int mt = w & 3;
    const int phh = w >> 2;

    float* Ob = out + (size_t)b * NCAND * DIM;
#pragma unroll
    for (int pp = 0; pp < 2; pp++) {
        const int pn = phh * 2 + pp;

        float ua[4][2][4];
#pragma unroll
        for (int ntt = 0; ntt < 4; ntt++)
#pragma unroll
            for (int n8 = 0; n8 < 2; n8++)
#pragma unroll
                for (int i = 0; i < 4; i++) ua[ntt][n8][i] = 0.f;

#pragma unroll
        for (int ks = 0; ks < 2; ks++) {
            const int arow = mt * 16 + ((g & 1) << 3) + rw;
            const int acol = ks * 16 + ((g >> 1) << 3);
            const uint32_t ao = SWZ((uint32_t)(arow * 128 + acol * 2));
            uint32_t am1[4], am2[4];
            ldsm4(am1, uW + ao);
            ldsm4(am2, uW + 8192 + ao);

            const int trow = ks * 16 + (lane & 7) + ((lane >> 3) & 1) * 8;
            const int tcolb = ((lane >> 4) & 1) * 8;
#pragma unroll
            for (int ntt = 0; ntt < 4; ntt++) {
                const uint32_t bo = pn * 4096 + SWZ((uint32_t)(trow * 128 + (ntt * 16 + tcolb) * 2));
                uint32_t bi1[4], bi2[4];
                ldsm4t(bi1, uI + bo);
                ldsm4t(bi2, uI + 16384 + bo);
#pragma unroll
                for (int n8 = 0; n8 < 2; n8++) {
                    float* c = ua[ntt][n8];
                    mma16816(c, am1, bi1[n8 * 2], bi1[n8 * 2 + 1]);
                    mma16816(c, am1, bi2[n8 * 2], bi2[n8 * 2 + 1]);
                    mma16816(c, am2, bi1[n8 * 2], bi1[n8 * 2 + 1]);
                }
            }
        }

#pragma unroll
        for (int ntt = 0; ntt < 4; ntt++) {
#pragma unroll
            for (int n8 = 0; n8 < 2; n8++) {
                const int d = pn * 64 + ntt * 16 + n8 * 8 + tig * 2;
                const int r0 = mt * 16 + gid;
                *(float2*)&Ob[(size_t)r0 * 256 + d]       = make_float2(ua[ntt][n8][0], ua[ntt][n8][1]);
                *(float2*)&Ob[(size_t)(r0 + 8) * 256 + d] = make_float2(ua[ntt][n8][2], ua[ntt][n8][3]);
            }
        }
    }
}

// ---------------------------------------------------------------------------
extern "C" void kernel_launch(void* const* d_in, const int* in_sizes, int n_in,
                              void* d_out, int out_size) {
    (void)in_sizes; (void)n_in; (void)out_size;
    const float* hist  = (const float*)d_in[0];
    const float* cand  = (const float*)d_in[2];
    const int*   numI  = (const int*)d_in[3];
    const int*   catC  = (const int*)d_in[4];
    const float* W     = (const float*)d_in[5];
    const float* codes = (const float*)d_in[6];
    float* out = (float*)d_out;

    static bool attr_set = false;
    if (!attr_set) {
        cudaFuncSetAttribute(k1_mma, cudaFuncAttributeMaxDynamicSharedMemorySize, K1_SMEM);
        cudaFuncSetAttribute(k24, cudaFuncAttributeMaxDynamicSharedMemorySize, K24_SMEM);
        attr_set = true;
    }

    kw_split<<<256, 256>>>(W);
    k1_mma<<<dim3(2, 400), 256, K1_SMEM>>>(hist);
    k2a_kernel<<<400, 128>>>(codes);
    k24<<<BSZ, 256, K24_SMEM>>>(hist, numI, cand, catC, out);
}

// round 14
// speedup vs baseline: 1.2702x; 1.0488x over previous
#include <cuda_runtime.h>
#include <cuda_fp16.h>
#include <math.h>
#include <stdint.h>

#define BSZ   512
#define LEN   100
#define NCAND 64
#define DIM   256
#define KIN   32

typedef unsigned long long u64;

// Scratch (no allocations allowed)
__device__ float  g_proj[BSZ * LEN * DIM];          // 52.4 MB
__device__ float  g_scores[BSZ * KIN * LEN];        // [b][k][l]

// ---- packed fp32x2 helpers --------------------------------------------------
__device__ __forceinline__ u64 ffma2(u64 a, u64 b, u64 c) {
    u64 d;
    asm("fma.rn.f32x2 %0, %1, %2, %3;" : "=l"(d) : "l"(a), "l"(b), "l"(c));
    return d;
}
__device__ __forceinline__ u64 packu(uint32_t a, uint32_t b) {
    u64 r;
    asm("mov.b64 %0, {%1, %2};" : "=l"(r) : "r"(a), "r"(b));
    return r;
}
__device__ __forceinline__ float2 unpack2(u64 v) {
    float2 r;
    asm("mov.b64 {%0, %1}, %2;" : "=f"(r.x), "=f"(r.y) : "l"(v));
    return r;
}

// ---- mma.sync helpers ---------------------------------------------------------
__device__ __forceinline__ uint32_t smem_u32(const void* p) {
    uint32_t a;
    asm("{ .reg .u64 t; cvta.to.shared.u64 t, %1; cvt.u32.u64 %0, t; }" : "=r"(a) : "l"(p));
    return a;
}
__device__ __forceinline__ void ldsm4(uint32_t* r, uint32_t addr) {
    asm volatile("ldmatrix.sync.aligned.m8n8.x4.shared.b16 {%0,%1,%2,%3}, [%4];"
                 : "=r"(r[0]), "=r"(r[1]), "=r"(r[2]), "=r"(r[3]) : "r"(addr) : "memory");
}
__device__ __forceinline__ void ldsm4t(uint32_t* r, uint32_t addr) {
    asm volatile("ldmatrix.sync.aligned.m8n8.x4.trans.shared.b16 {%0,%1,%2,%3}, [%4];"
                 : "=r"(r[0]), "=r"(r[1]), "=r"(r[2]), "=r"(r[3]) : "r"(addr) : "memory");
}
__device__ __forceinline__ void mma16816(float* d, const uint32_t* a, uint32_t b0, uint32_t b1) {
    asm volatile("mma.sync.aligned.m16n8k16.row.col.f32.f16.f16.f32 "
                 "{%0,%1,%2,%3}, {%4,%5,%6,%7}, {%8,%9}, {%0,%1,%2,%3};"
                 : "+f"(d[0]), "+f"(d[1]), "+f"(d[2]), "+f"(d[3])
                 : "r"(a[0]), "r"(a[1]), "r"(a[2]), "r"(a[3]), "r"(b0), "r"(b1));
}
__device__ __forceinline__ void cpasync16(uint32_t smem_addr, const void* gptr) {
    asm volatile("cp.async.ca.shared.global [%0], [%1], 16;"
                 :: "r"(smem_addr), "l"(gptr) : "memory");
}
#define CP_COMMIT() asm volatile("cp.async.commit_group;" ::: "memory")
#define CP_WAIT(n)  asm volatile("cp.async.wait_group %0;" :: "n"(n) : "memory")

#define SWZ(o) ((o) ^ (((o) >> 3) & 0x70))

__device__ __forceinline__ uint32_t h2_u32(__half a, __half b) {
    __half2 t(a, b);
    return *reinterpret_cast<uint32_t*>(&t);
}
__device__ __forceinline__ void split_pack(float x, float y, uint32_t& lo, uint32_t& hi) {
    const __half ax = __float2half_rn(x), ay = __float2half_rn(y);
    const __half bx = __float2half_rn(x - __half2float(ax));
    const __half by = __float2half_rn(y - __half2float(ay));
    lo = h2_u32(ax, ay);
    hi = h2_u32(bx, by);
}

// ---------------------------------------------------------------------------
// K1: proj = tanh(hist @ W^T) via mma.sync fp16, 2-level split (3 passes).
// W split inline (no kw_split kernel).
// ---------------------------------------------------------------------------
#define A_OFF  0
#define B_OFF  32768
#define LVL    16384
#define K1_SMEM (65536 + 1024)

__global__ void __launch_bounds__(256, 2) k1_mma(const float* __restrict__ hist,
                                                 const float* __restrict__ W) {
    extern __shared__ char smem_raw[];
    const int tid = threadIdx.x;
    const int wid = tid >> 5;
    const int lane = tid & 31;
    const int warp_m = wid >> 2;
    const int warp_n = wid & 3;
    const int m0 = blockIdx.y * 128;
    const int n0 = blockIdx.x * 128;

    const uint32_t sb_raw = smem_u32(smem_raw);
    const uint32_t sb = (sb_raw + 1023u) & ~1023u;
    char* smem = smem_raw + (sb - sb_raw);

    const int g  = lane >> 3;
    const int rw = lane & 7;

    float acc[4][4][4];
#pragma unroll
    for (int mt = 0; mt < 4; mt++)
#pragma unroll
        for (int nt = 0; nt < 4; nt++)
#pragma unroll
            for (int i = 0; i < 4; i++) acc[mt][nt][i] = 0.f;

    for (int kc = 0; kc < 4; kc++) {
#pragma unroll
        for (int t = 0; t < 8; t++) {
            const int idx = tid + t * 256;
            const int r = idx >> 4, c4 = idx & 15;
            const float4 a = __ldg((const float4*)&hist[(size_t)(m0 + r) * 256 + kc * 64 + c4 * 4]);
            uint32_t lx, hx, ly, hy;
            split_pack(a.x, a.y, lx, hx);
            split_pack(a.z, a.w, ly, hy);
            const uint32_t off = SWZ((uint32_t)(r * 128 + c4 * 8));
            *(uint2*)(smem + A_OFF + off)       = make_uint2(lx, ly);
            *(uint2*)(smem + A_OFF + LVL + off) = make_uint2(hx, hy);
        }
        // B: W fp32 -> split inline
#pragma unroll
        for (int t = 0; t < 8; t++) {
            const int idx = tid + t * 256;
            const int n = idx >> 4, c4 = idx & 15;
            const float4 a = __ldg((const float4*)&W[(size_t)(n0 + n) * 256 + kc * 64 + c4 * 4]);
            uint32_t lx, hx, ly, hy;
            split_pack(a.x, a.y, lx, hx);
            split_pack(a.z, a.w, ly, hy);
            const uint32_t off = SWZ((uint32_t)(n * 128 + c4 * 8));
            *(uint2*)(smem + B_OFF + off)       = make_uint2(lx, ly);
            *(uint2*)(smem + B_OFF + LVL + off) = make_uint2(hx, hy);
        }
        __syncthreads();

#pragma unroll
        for (int ks = 0; ks < 4; ks++) {
            const int k0 = ks * 16;
            uint32_t aoff[4], boff[2];
#pragma unroll
            for (int mt = 0; mt < 4; mt++) {
                const int row = warp_m * 64 + mt * 16 + ((g & 1) << 3) + rw;
                const int kk  = k0 + ((g >> 1) << 3);
                aoff[mt] = sb + A_OFF + SWZ((uint32_t)(row * 128 + kk * 2));
            }
#pragma unroll
            for (int nt2 = 0; nt2 < 2; nt2++) {
                const int row = warp_n * 32 + nt2 * 16 + ((g >> 1) << 3) + rw;
                const int kk  = k0 + ((g & 1) << 3);
                boff[nt2] = sb + B_OFF + SWZ((uint32_t)(row * 128 + kk * 2));
            }

            uint32_t a0[4][4], a1[4][4], b0[2][4], b1[2][4];
#pragma unroll
            for (int mt = 0; mt < 4; mt++) { ldsm4(a0[mt], aoff[mt]); ldsm4(a1[mt], aoff[mt] + LVL); }
#pragma unroll
            for (int nt2 = 0; nt2 < 2; nt2++) { ldsm4(b0[nt2], boff[nt2]); ldsm4(b1[nt2], boff[nt2] + LVL); }

#pragma unroll
            for (int mt = 0; mt < 4; mt++)
#pragma unroll
                for (int nt = 0; nt < 4; nt++) {
                    const int h = nt >> 1, q = (nt & 1) * 2;
                    mma16816(acc[mt][nt], a0[mt], b0[h][q], b0[h][q + 1]);
                    mma16816(acc[mt][nt], a0[mt], b1[h][q], b1[h][q + 1]);
                    mma16816(acc[mt][nt], a1[mt], b0[h][q], b0[h][q + 1]);
                }
        }
        __syncthreads();
    }

    const int gid = lane >> 2, tig = lane & 3;
#pragma unroll
    for (int mt = 0; mt < 4; mt++) {
#pragma unroll
        for (int nt = 0; nt < 4; nt++) {
            const int row = m0 + warp_m * 64 + mt * 16 + gid;
            const int col = n0 + warp_n * 32 + nt * 8 + tig * 2;
            float2 v0, v1;
            v0.x = tanhf(acc[mt][nt][0]); v0.y = tanhf(acc[mt][nt][1]);
            v1.x = tanhf(acc[mt][nt][2]); v1.y = tanhf(acc[mt][nt][3]);
            *(float2*)&g_proj[(size_t)row * 256 + col]       = v0;
            *(float2*)&g_proj[(size_t)(row + 8) * 256 + col] = v1;
        }
    }
}

// ---------------------------------------------------------------------------
// K2a: scores = g_proj @ codes^T  (unchanged)
// ---------------------------------------------------------------------------
__global__ void __launch_bounds__(128) k2a_kernel(const float* __restrict__ codes) {
    __shared__ __align__(16) char Asm[2][16384];
    __shared__ __align__(16) char Bsm[2][4096];

    const int tid = threadIdx.x;
    const int w = tid >> 5;
    const int lane = tid & 31;
    const int m0 = blockIdx.x * 128;
    const int g = lane >> 3, rw = lane & 7;
    const uint32_t sbA = smem_u32(Asm);
    const uint32_t sbB = smem_u32(Bsm);

    float acc[2][4][4];
#pragma unroll
    for (int mt = 0; mt < 2; mt++)
#pragma unroll
        for (int nt = 0; nt < 4; nt++)
#pragma unroll
            for (int i = 0; i < 4; i++) acc[mt][nt][i] = 0.f;

    for (int kc = 0; kc < 4; kc++) {
#pragma unroll
        for (int t = 0; t < 16; t++) {
            const int idx = tid + t * 128;
            const int r = idx >> 4, c4 = idx & 15;
            const float4 a = __ldg((const float4*)&g_proj[(size_t)(m0 + r) * 256 + kc * 64 + c4 * 4]);
            uint32_t lx, hx, ly, hy;
            split_pack(a.x, a.y, lx, hx);
            split_pack(a.z, a.w, ly, hy);
            const uint32_t off = SWZ((uint32_t)(r * 128 + c4 * 8));
            *(uint2*)(Asm[0] + off) = make_uint2(lx, ly);
            *(uint2*)(Asm[1] + off) = make_uint2(hx, hy);
        }
#pragma unroll
        for (int t = 0; t < 4; t++) {
            const int idx = tid + t * 128;
            const int r = idx >> 4, c4 = idx & 15;
            const float4 a = __ldg((const float4*)&codes[(size_t)r * 256 + kc * 64 + c4 * 4]);
            uint32_t lx, hx, ly, hy;
            split_pack(a.x, a.y, lx, hx);
            split_pack(a.z, a.w, ly, hy);
            const uint32_t off = SWZ((uint32_t)(r * 128 + c4 * 8));
            *(uint2*)(Bsm[0] + off) = make_uint2(lx, ly);
            *(uint2*)(Bsm[1] + off) = make_uint2(hx, hy);
        }
        __syncthreads();

#pragma unroll
        for (int ks = 0; ks < 4; ks++) {
            const int k0 = ks * 16;
            uint32_t aoff[2], boff[2];
#pragma unroll
            for (int mt = 0; mt < 2; mt++) {
                const int row = w * 32 + mt * 16 + ((g & 1) << 3) + rw;
                aoff[mt] = sbA + SWZ((uint32_t)(row * 128 + (k0 + ((g >> 1) << 3)) * 2));
            }
#pragma unroll
            for (int nt2 = 0; nt2 < 2; nt2++) {
                const int row = nt2 * 16 + ((g >> 1) << 3) + rw;
                boff[nt2] = sbB + SWZ((uint32_t)(row * 128 + (k0 + ((g & 1) << 3)) * 2));
            }
            uint32_t a0[2][4], a1[2][4], b0[2][4], b1[2][4];
#pragma unroll
            for (int mt = 0; mt < 2; mt++) { ldsm4(a0[mt], aoff[mt]); ldsm4(a1[mt], aoff[mt] + 16384); }
#pragma unroll
            for (int nt2 = 0; nt2 < 2; nt2++) { ldsm4(b0[nt2], boff[nt2]); ldsm4(b1[nt2], boff[nt2] + 4096); }
#pragma unroll
            for (int mt = 0; mt < 2; mt++)
#pragma unroll
                for (int nt = 0; nt < 4; nt++) {
                    const int h = nt >> 1, q = (nt & 1) * 2;
                    mma16816(acc[mt][nt], a0[mt], b0[h][q], b0[h][q + 1]);
                    mma16816(acc[mt][nt], a0[mt], b1[h][q], b1[h][q + 1]);
                    mma16816(acc[mt][nt], a1[mt], b0[h][q], b0[h][q + 1]);
                    mma16816(acc[mt][nt], a1[mt], b1[h][q], b1[h][q + 1]);
                }
        }
        __syncthreads();
    }

    const int gid = lane >> 2, tig = lane & 3;
#pragma unroll
    for (int mt = 0; mt < 2; mt++) {
#pragma unroll
        for (int nt = 0; nt < 4; nt++) {
            const int col = nt * 8 + tig * 2;
#pragma unroll
            for (int half = 0; half < 2; half++) {
                const int M = m0 + w * 32 + mt * 16 + gid + half * 8;
                const int b = M / 100, l = M - b * 100;
                float* dst = g_scores + (size_t)b * 3200 + l;
                dst[(size_t)col * 100]       = acc[mt][nt][half * 2];
                dst[(size_t)(col + 1) * 100] = acc[mt][nt][half * 2 + 1];
            }
        }
    }
}

// ---------------------------------------------------------------------------
// K24: per-batch fused  softmax -> interests(mma) -> w(fp32) -> rank -> user(mma).
// cp.async double-buffered candidate loads in the w phase.
// SMEM (dyn, 1024-aligned):
//   ph1-3: Asm [0,16K) | Bsm [16K,48K)
//   ph4:   if32 [0,32K)
//   ph5:   cand0 [0,8K) cand1 [8K,16K) partial [16K,24K) wmaskT [24K,32K)
//   ph6-7: wmsm [0,16K) (over cand), wmaskT live, ism [48K,80K) (ph4-7)
// ---------------------------------------------------------------------------
#define O_ASM   0
#define O_BSM   16384
#define O_IF32  0
#define O_CAND0 0
#define O_CAND1 8192
#define O_PART  16384
#define O_WMT   24576
#define O_WMS   0
#define O_ISM   49152
#define K24_SMEM (81920 + 1024)

__global__ void __launch_bounds__(256, 2) k24(const float* __restrict__ hist,
                                              const int* __restrict__ numInt,
                                              const float* __restrict__ cand,
                                              const int* __restrict__ catCnt,
                                              float* __restrict__ out) {
    extern __shared__ char raw[];
    const int b = blockIdx.x;
    const int tid = threadIdx.x;
    const int w = tid >> 5;
    const int lane = tid & 31;
    const int g = lane >> 3, rw = lane & 7;
    const int gid = lane >> 2, tig = lane & 3;

    const uint32_t sbr = smem_u32(raw);
    const uint32_t sb = (sbr + 1023u) & ~1023u;
    char* s = raw + (sb - sbr);

    char* Asm = s + O_ASM;
    char* Bsm = s + O_BSM;
    char* ism = s + O_ISM;
    float* if32 = (float*)(s + O_IF32);
    const uint32_t uA = sb + O_ASM, uB = sb + O_BSM, uI = sb + O_ISM;

    // ================= Phase 1: softmax (sc overlays Bsm) =================
    float* sc = (float*)Bsm;
    {
        const float* src = g_scores + (size_t)b * 3200;
        for (int idx = tid; idx < 3200; idx += 256) sc[idx] = src[idx];
    }
    __syncthreads();
    {
        const int ni = numInt[b];
        for (int k = w; k < 32; k += 8) {
            if (k >= ni) {
                for (int l = lane; l < LEN; l += 32) sc[k * 100 + l] = 0.01f;
            } else {
                float m = -3.4e38f;
                for (int l = lane; l < LEN; l += 32) m = fmaxf(m, sc[k * 100 + l]);
#pragma unroll
                for (int off = 16; off; off >>= 1)
                    m = fmaxf(m, __shfl_xor_sync(0xffffffffu, m, off));
                float ssum = 0.f;
                for (int l = lane; l < LEN; l += 32) {
                    float e = expf(sc[k * 100 + l] - m);
                    sc[k * 100 + l] = e;
                    ssum += e;
                }
#pragma unroll
                for (int off = 16; off; off >>= 1) ssum += __shfl_xor_sync(0xffffffffu, ssum, off);
                for (int l = lane; l < LEN; l += 32) sc[k * 100 + l] = sc[k * 100 + l] / ssum;
            }
        }
    }
    __syncthreads();

    // ================= Phase 2: attn splits -> Asm =================
    for (int idx = tid; idx < 2048; idx += 256) {
        const int k = idx >> 6;
        const int l2 = (idx & 63) * 2;
        const float v0 = (l2 < 100) ? sc[k * 100 + l2] : 0.f;
        const float v1 = (l2 + 1 < 100) ? sc[k * 100 + l2 + 1] : 0.f;
        uint32_t lo, hi;
        split_pack(v0, v1, lo, hi);
        const int h = l2 >> 6, ll = l2 & 63;
        const uint32_t off = SWZ((uint32_t)((h * 32 + k) * 128 + ll * 2));
        *(uint32_t*)(Asm + off)        = lo;
        *(uint32_t*)(Asm + 8192 + off) = hi;
    }
    __syncthreads();

    // ================= Phase 3: interests mma (8-warp, 4-pass) =================
    const int pnl = w >> 1;
    const int sub = w & 1;
    float acc[2][2][2][4];
#pragma unroll
    for (int mt = 0; mt < 2; mt++)
#pragma unroll
        for (int ntt = 0; ntt < 2; ntt++)
#pragma unroll
            for (int n8 = 0; n8 < 2; n8++)
#pragma unroll
                for (int i = 0; i < 4; i++) acc[mt][ntt][n8][i] = 0.f;

    const float* Hb = hist + (size_t)b * LEN * DIM;
    for (int ch = 0; ch < 4; ch++) {
        const int l0 = ch * 32;
#pragma unroll
        for (int t = 0; t < 8; t++) {
            const int idx = tid + t * 256;
            const int lr = idx >> 6, c4 = idx & 63;
            const int l = l0 + lr;
            float4 a = make_float4(0.f, 0.f, 0.f, 0.f);
            if (l < LEN) a = __ldg((const float4*)&Hb[(size_t)l * 256 + c4 * 4]);
            uint32_t lx, hx, ly, hy;
            split_pack(a.x, a.y, lx, hx);
            split_pack(a.z, a.w, ly, hy);
            const int d = c4 * 4;
            const int p = d >> 6, dcol = d & 63;
            const uint32_t off = p * 4096 + SWZ((uint32_t)(lr * 128 + dcol * 2));
            *(uint2*)(Bsm + off)         = make_uint2(lx, ly);
            *(uint2*)(Bsm + 16384 + off) = make_uint2(hx, hy);
        }
        __syncthreads();

#pragma unroll
        for (int ks2 = 0; ks2 < 2; ks2++) {
            const int kk = l0 + ks2 * 16;
            const int half = kk >> 6, lloc = kk & 63;

            uint32_t a0[2][4], a1[2][4];
#pragma unroll
            for (int mt = 0; mt < 2; mt++) {
                const int row = mt * 16 + ((g & 1) << 3) + rw;
                const uint32_t ao = SWZ((uint32_t)((half * 32 + row) * 128 + (lloc + ((g >> 1) << 3)) * 2));
                ldsm4(a0[mt], uA + ao);
                ldsm4(a1[mt], uA + 8192 + ao);
            }

            const int trow = ks2 * 16 + (lane & 7) + ((lane >> 3) & 1) * 8;
            const int tcolb = ((lane >> 4) & 1) * 8;
#pragma unroll
            for (int ntt = 0; ntt < 2; ntt++) {
                const int ntg = sub * 2 + ntt;
                const uint32_t bo = pnl * 4096 + SWZ((uint32_t)(trow * 128 + (ntg * 16 + tcolb) * 2));
                uint32_t bl0[4], bl1[4];
                ldsm4t(bl0, uB + bo);
                ldsm4t(bl1, uB + 16384 + bo);
#pragma unroll
                for (int mt = 0; mt < 2; mt++) {
                    float* c0 = acc[mt][ntt][0];
                    float* c1 = acc[mt][ntt][1];
                    mma16816(c0, a0[mt], bl0[0], bl0[1]);
                    mma16816(c0, a0[mt], bl1[0], bl1[1]);
                    mma16816(c0, a1[mt], bl0[0], bl0[1]);
                    mma16816(c0, a1[mt], bl1[0], bl1[1]);
                    mma16816(c1, a0[mt], bl0[2], bl0[3]);
                    mma16816(c1, a0[mt], bl1[2], bl1[3]);
                    mma16816(c1, a1[mt], bl0[2], bl0[3]);
                    mma16816(c1, a1[mt], bl1[2], bl1[3]);
                }
            }
        }
        __syncthreads();
    }

    // ================= Phase 4: interests -> if32 + ism =================
#pragma unroll
    for (int mt = 0; mt < 2; mt++) {
#pragma unroll
        for (int ntt = 0; ntt < 2; ntt++) {
            const int ntg = sub * 2 + ntt;
#pragma unroll
            for (int n8 = 0; n8 < 2; n8++) {
                const int d = pnl * 64 + ntg * 16 + n8 * 8 + tig * 2;
#pragma unroll
                for (int hh = 0; hh < 2; hh++) {
                    const int kk = mt * 16 + gid + hh * 8;
                    const float vx = acc[mt][ntt][n8][hh * 2], vy = acc[mt][ntt][n8][hh * 2 + 1];
                    *(float2*)&if32[kk * 256 + d] = make_float2(vx, vy);
                    uint32_t lo, hi;
                    split_pack(vx, vy, lo, hi);
                    const int dloc = d & 63;
                    const uint32_t off = pnl * 4096 + SWZ((uint32_t)(kk * 128 + dloc * 2));
                    *(uint32_t*)(ism + off)         = lo;
                    *(uint32_t*)(ism + 16384 + off) = hi;
                }
            }
        }
    }
    __syncthreads();

    // ================= Phase 5: w-GEMM (exact fp32) + rank, cp.async pipeline ==
    float* partial = (float*)(s + O_PART);
    float* wmaskT  = (float*)(s + O_WMT);
    const uint32_t uC0 = sb + O_CAND0, uC1 = sb + O_CAND1;

    u64 ireg2[16];
    {
        const u64* ibase = (const u64*)(if32 + lane * 256 + w * 32);
#pragma unroll
        for (int j = 0; j < 16; j++) ireg2[j] = ibase[j];
    }
    __syncthreads();   // if32 dead; cand buffers overlay it

    const int cc = catCnt[b];
    int dynK = (int)ceilf(log2f(8.0f * (float)cc));
    dynK = dynK < 1 ? 1 : (dynK > 32 ? 32 : dynK);

    const float* Cb = cand + (size_t)b * NCAND * DIM;

    // prologue: rows 0..7 -> buf0
    cpasync16(uC0 + tid * 16, Cb + tid * 4);
    cpasync16(uC0 + (tid + 256) * 16, Cb + (size_t)(tid + 256) * 4);
    CP_COMMIT();

    for (int n0 = 0; n0 < 64; n0 += 8) {
        const int buf = (n0 >> 3) & 1;
        const uint32_t uCur = buf ? uC1 : uC0;
        if (n0 + 8 < 64) {
            const uint32_t uNxt = buf ? uC0 : uC1;
            const float* src = Cb + (size_t)(n0 + 8) * DIM;
            cpasync16(uNxt + tid * 16, src + tid * 4);
            cpasync16(uNxt + (tid + 256) * 16, src + (size_t)(tid + 256) * 4);
            CP_COMMIT();
            CP_WAIT(1);
        } else {
            CP_WAIT(0);
        }
        __syncthreads();

        const uint4* rbase4 = (const uint4*)(s + (buf ? O_CAND1 : O_CAND0));
        u64 p[8];
#pragma unroll
        for (int r = 0; r < 8; r++) p[r] = 0ull;
#pragma unroll
        for (int j4 = 0; j4 < 8; j4++) {
            const u64 iv0 = ireg2[j4 * 2], iv1 = ireg2[j4 * 2 + 1];
            const int coff = w * 8 + j4;
#pragma unroll
            for (int r = 0; r < 8; r++) {
                const uint4 v = rbase4[r * 64 + coff];
                p[r] = ffma2(iv0, packu(v.x, v.y), p[r]);
                p[r] = ffma2(iv1, packu(v.z, v.w), p[r]);
            }
        }
#pragma unroll
        for (int r = 0; r < 8; r++) {
            float2 t = unpack2(p[r]);
            partial[w * 256 + r * 32 + lane] = t.x + t.y;
        }
        __syncthreads();

        {
            const int k = lane, r = w;
            float ssum = 0.f;
#pragma unroll
            for (int ww = 0; ww < 8; ww++) ssum += partial[ww * 256 + r * 32 + k];
            wmaskT[(n0 + r) * 32 + k] = ssum;
        }
        __syncwarp();

        {
            const float wi = wmaskT[(n0 + w) * 32 + lane];
            int rank = 0;
#pragma unroll
            for (int j = 0; j < 32; j++) {
                const float wj = __shfl_sync(0xffffffffu, wi, j);
                rank += (wj > wi) || (wj == wi && j < lane);
            }
            wmaskT[(n0 + w) * 32 + lane] = (rank < dynK) ? wi : 0.f;
        }
        __syncthreads();
    }

    // ================= Phase 6: wmask fp16 splits (over dead cand bufs) =========
    char* wmsm = s + O_WMS;
    const uint32_t uW = sb + O_WMS;
    for (int idx = tid; idx < 2048; idx += 256) {
        const int r = idx >> 5, c = idx & 31;
        const float v = wmaskT[r * 32 + c];
        const __half m1 = __float2half_rn(v);
        const __half m2 = __float2half_rn(v - __half2float(m1));
        const uint32_t off = SWZ((uint32_t)(r * 128 + c * 2));
        *(__half*)(wmsm + off)        = m1;
        *(__half*)(wmsm + 8192 + off) = m2;
    }
    __syncthreads();

    // ================= Phase 7: user mma (3-pass) =================
    const int mt = w & 3;
    const int phh = w >> 2;

    float* Ob = out + (size_t)b * NCAND * DIM;
#pragma unroll
    for (int pp = 0; pp < 2; pp++) {
        const int pn = phh * 2 + pp;

        float ua[4][2][4];
#pragma unroll
        for (int ntt = 0; ntt < 4; ntt++)
#pragma unroll
            for (int n8 = 0; n8 < 2; n8++)
#pragma unroll
                for (int i = 0; i < 4; i++) ua[ntt][n8][i] = 0.f;

#pragma unroll
        for (int ks = 0; ks < 2; ks++) {
            const int arow = mt * 16 + ((g & 1) << 3) + rw;
            const int acol = ks * 16 + ((g >> 1) << 3);
            const uint32_t ao = SWZ((uint32_t)(arow * 128 + acol * 2));
            uint32_t am1[4], am2[4];
            ldsm4(am1, uW + ao);
            ldsm4(am2, uW + 8192 + ao);

            const int trow = ks * 16 + (lane & 7) + ((lane >> 3) & 1) * 8;
            const int tcolb = ((lane >> 4) & 1) * 8;
#pragma unroll
            for (int ntt = 0; ntt < 4; ntt++) {
                const uint32_t bo = pn * 4096 + SWZ((uint32_t)(trow * 128 + (ntt * 16 + tcolb) * 2));
                uint32_t bi1[4], bi2[4];
                ldsm4t(bi1, uI + bo);
                ldsm4t(bi2, uI + 16384 + bo);
#pragma unroll
                for (int n8 = 0; n8 < 2; n8++) {
                    float* c = ua[ntt][n8];
                    mma16816(c, am1, bi1[n8 * 2], bi1[n8 * 2 + 1]);
                    mma16816(c, am1, bi2[n8 * 2], bi2[n8 * 2 + 1]);
                    mma16816(c, am2, bi1[n8 * 2], bi1[n8 * 2 + 1]);
                }
            }
        }

#pragma unroll
        for (int ntt = 0; ntt < 4; ntt++) {
#pragma unroll
            for (int n8 = 0; n8 < 2; n8++) {
                const int d = pn * 64 + ntt * 16 + n8 * 8 + tig * 2;
                const int r0 = mt * 16 + gid;
                *(float2*)&Ob[(size_t)r0 * 256 + d]       = make_float2(ua[ntt][n8][0], ua[ntt][n8][1]);
                *(float2*)&Ob[(size_t)(r0 + 8) * 256 + d] = make_float2(ua[ntt][n8][2], ua[ntt][n8][3]);
            }
        }
    }
}

// ---------------------------------------------------------------------------
extern "C" void kernel_launch(void* const* d_in, const int* in_sizes, int n_in,
                              void* d_out, int out_size) {
    (void)in_sizes; (void)n_in; (void)out_size;
    const float* hist  = (const float*)d_in[0];
    const float* cand  = (const float*)d_in[2];
    const int*   numI  = (const int*)d_in[3];
    const int*   catC  = (const int*)d_in[4];
    const float* W     = (const float*)d_in[5];
    const float* codes = (const float*)d_in[6];
    float* out = (float*)d_out;

    static bool attr_set = false;
    if (!attr_set) {
        cudaFuncSetAttribute(k1_mma, cudaFuncAttributeMaxDynamicSharedMemorySize, K1_SMEM);
        cudaFuncSetAttribute(k24, cudaFuncAttributeMaxDynamicSharedMemorySize, K24_SMEM);
        attr_set = true;
    }

    k1_mma<<<dim3(2, 400), 256, K1_SMEM>>>(hist, W);
    k2a_kernel<<<400, 128>>>(codes);
    k24<<<BSZ, 256, K24_SMEM>>>(hist, numI, cand, catC, out);
}